// round 10
// baseline (speedup 1.0000x reference)
#include <cuda_runtime.h>
#include <cuda_fp16.h>
#include <math.h>
#include <stdint.h>

#define EMBED 768
#define FF    3072
#define BATCH 8
#define SEQ   1024
#define TOK   (BATCH * SEQ)   // 8192
#define NQKV  (3 * EMBED)     // 2304

typedef __half fp16;

// ============================ scratch buffers ================================
__device__ __align__(16) fp16  g_xhi[TOK * EMBED],  g_xlo[TOK * EMBED];
__device__ __align__(16) fp16  g_Wqkvh[(long)NQKV * EMBED];
__device__ __align__(16) float g_bqkv[NQKV];
__device__ __align__(16) fp16  g_W1Th[(long)FF * EMBED];
__device__ __align__(16) fp16  g_W2Th[(long)EMBED * FF];
__device__ __align__(16) fp16  g_QKVh[(long)TOK * NQKV], g_QKVl[(long)TOK * NQKV];
__device__ __align__(16) fp16  g_VTh[(long)BATCH * EMBED * SEQ];
__device__ __align__(16) float g_S[(long)BATCH * SEQ * SEQ];
__device__ __align__(16) fp16  g_Phi[(long)BATCH * SEQ * SEQ], g_Plo[(long)BATCH * SEQ * SEQ];
__device__ __align__(16) float g_attnP[2L * TOK * EMBED];
__device__ __align__(16) float g_x1[TOK * EMBED];
__device__ __align__(16) fp16  g_x1hi[TOK * EMBED], g_x1lo[TOK * EMBED];
__device__ __align__(16) fp16  g_hhi[(long)TOK * FF], g_hlo[(long)TOK * FF];
__device__ __align__(16) float g_fP[3L * TOK * EMBED];

// ============================ PTX helpers ====================================
__device__ __forceinline__ uint32_t smem_u32(const void* p) {
    uint32_t a;
    asm("{ .reg .u64 t; cvta.to.shared.u64 t, %1; cvt.u32.u64 %0, t; }" : "=r"(a) : "l"(p));
    return a;
}
__device__ __forceinline__ void cp16(uint32_t dst, const void* src) {
    asm volatile("cp.async.cg.shared.global [%0], [%1], 16;" :: "r"(dst), "l"(src));
}
#define CP_COMMIT() asm volatile("cp.async.commit_group;" ::: "memory")

__device__ __forceinline__ void ldm_x4(uint32_t* r, uint32_t addr) {
    asm volatile("ldmatrix.sync.aligned.m8n8.x4.shared.b16 {%0,%1,%2,%3}, [%4];"
                 : "=r"(r[0]), "=r"(r[1]), "=r"(r[2]), "=r"(r[3]) : "r"(addr));
}
__device__ __forceinline__ void mma16816(float* d, const uint32_t* a, uint32_t b0, uint32_t b1) {
    asm volatile(
        "mma.sync.aligned.m16n8k16.row.col.f32.f16.f16.f32 "
        "{%0,%1,%2,%3}, {%4,%5,%6,%7}, {%8,%9}, {%0,%1,%2,%3};"
        : "+f"(d[0]), "+f"(d[1]), "+f"(d[2]), "+f"(d[3])
        : "r"(a[0]), "r"(a[1]), "r"(a[2]), "r"(a[3]), "r"(b0), "r"(b1));
}
#define SWZ128(o) ((o) ^ (((o) >> 3) & 0x70))

__device__ __forceinline__ float gelu_exact(float v) {
    return 0.5f * v * (1.0f + erff(v * 0.7071067811865475f));
}
__device__ __forceinline__ ushort h2u(fp16 h) { return __half_as_ushort(h); }

// ============================ mma GEMM =======================================
// C[M,N] = (Ahi+Alo)[M,K] @ fp16(B)[N,K]^T   (both K-major row-major)
// 2-pass fp16 split: full-precision A x fp16-rounded B.
// CTA 256x128, 512 threads, warp grid 4Mx4N (warp tile 64x32), BK=64, 2 stages.
// Stage: Ahi 32K | Alo 32K | Bhi 16K = 80K; 2 stages = 160K.
// blockIdx.z = batch*ksplit + split;  K = per-split K length.
// EPI: 1 bias->(hi,lo) | 2 scale->fp32 | 3 bias+gelu->(hi,lo)
// VOUT (with EPI=1): CTAs with col0>=1536 write transposed VT (hi only).
#define BT_M 256
#define BT_N 128
#define BK   64
#define BSTAGE 81920
#define BSMEM_TOTAL (2 * BSTAGE)

template <int EPI, bool VOUT>
__global__ __launch_bounds__(512, 1)
void mma_gemm_big(const fp16* __restrict__ Ahi, const fp16* __restrict__ Alo, long ldA, long bsA,
                  const fp16* __restrict__ Bhi, long ldB, long bsB,
                  float* __restrict__ C, fp16* __restrict__ Chi, fp16* __restrict__ Clo,
                  long ldC, long bsC, const float* __restrict__ bias, float scale, int K,
                  int ksplit, long spStrideC, fp16* __restrict__ VTh)
{
    extern __shared__ char smem[];
    const uint32_t sbase = smem_u32(smem);
    const int tid  = threadIdx.x;
    const int bz   = blockIdx.z;
    const int sp   = bz % ksplit;
    const int bt   = bz / ksplit;
    const long koff = (long)sp * K;
    const int row0 = blockIdx.y * BT_M;
    const int col0 = blockIdx.x * BT_N;

    const fp16* Ah = Ahi + (long)bt * bsA + koff;
    const fp16* Al = Alo + (long)bt * bsA + koff;
    const fp16* Bh = Bhi + (long)bt * bsB + koff;

    const int NC = K / BK;

    auto load_stage = [&](int buf, int k0) {
        const uint32_t sb = sbase + (uint32_t)buf * BSTAGE;
        #pragma unroll
        for (int i = 0; i < 4; i++) {            // A: 2048 granules per half
            const int g = tid + 512 * i;
            const int r = g >> 3, c = g & 7;
            const uint32_t off = SWZ128((uint32_t)(r * 128 + c * 16));
            const long ai = (long)(row0 + r) * ldA + k0 + c * 8;
            cp16(sb + off,         Ah + ai);
            cp16(sb + 32768 + off, Al + ai);
        }
        #pragma unroll
        for (int i = 0; i < 2; i++) {            // B: 1024 granules (hi only)
            const int g = tid + 512 * i;
            const int r = g >> 3, c = g & 7;
            const uint32_t off = SWZ128((uint32_t)(r * 128 + c * 16));
            const long bi = (long)(col0 + r) * ldB + k0 + c * 8;
            cp16(sb + 65536 + off, Bh + bi);
        }
    };

    load_stage(0, 0);
    CP_COMMIT();
    if (NC > 1) { load_stage(1, BK); CP_COMMIT(); }

    const int w    = tid >> 5;
    const int lane = tid & 31;
    const int wm   = w & 3;            // rows wm*64
    const int wn   = w >> 2;           // cols wn*32
    const int q    = lane >> 3;
    const int r8   = lane & 7;

    float acc[4][4][4];
    #pragma unroll
    for (int i = 0; i < 4; i++)
        #pragma unroll
        for (int j = 0; j < 4; j++)
            #pragma unroll
            for (int v = 0; v < 4; v++) acc[i][j][v] = 0.0f;

    for (int c = 0; c < NC; c++) {
        if (c + 1 < NC) asm volatile("cp.async.wait_group 1;" ::: "memory");
        else            asm volatile("cp.async.wait_group 0;" ::: "memory");
        __syncthreads();

        const uint32_t sb = sbase + (uint32_t)(c & 1) * BSTAGE;
        #pragma unroll
        for (int ks = 0; ks < 4; ks++) {
            uint32_t bhf[2][4];
            #pragma unroll
            for (int p = 0; p < 2; p++) {
                const int nn = wn * 32 + p * 16 + (q >> 1) * 8 + r8;
                const int cc = 2 * ks + (q & 1);
                ldm_x4(bhf[p], sb + 65536 + SWZ128((uint32_t)(nn * 128 + cc * 16)));
            }
            #pragma unroll
            for (int am = 0; am < 4; am++) {
                uint32_t ah[4], al[4];
                const int rr = wm * 64 + am * 16 + (q & 1) * 8 + r8;
                const int cc = 2 * ks + (q >> 1);
                const uint32_t off = SWZ128((uint32_t)(rr * 128 + cc * 16));
                ldm_x4(ah, sb + off);
                ldm_x4(al, sb + 32768 + off);
                #pragma unroll
                for (int bn = 0; bn < 4; bn++) {
                    const int p = bn >> 1, hf = (bn & 1) * 2;
                    mma16816(acc[am][bn], ah, bhf[p][hf], bhf[p][hf + 1]);
                    mma16816(acc[am][bn], al, bhf[p][hf], bhf[p][hf + 1]);
                }
            }
        }
        __syncthreads();
        if (c + 2 < NC) {
            load_stage(c & 1, (c + 2) * BK);
            CP_COMMIT();
        }
    }

    // -------- epilogue --------
    const int gg = lane >> 2, t = lane & 3;
    float* Cp = (EPI == 2) ? C + (long)bt * bsC + (long)sp * spStrideC : nullptr;
    fp16* Hp  = (EPI == 1 || EPI == 3) ? Chi + (long)bt * bsC : nullptr;
    fp16* Lp  = (EPI == 1 || EPI == 3) ? Clo + (long)bt * bsC : nullptr;
    const bool vout = VOUT && (col0 >= 2 * EMBED);

    #pragma unroll
    for (int am = 0; am < 4; am++) {
        const long r0 = row0 + wm * 64 + am * 16 + gg;
        const long r1 = r0 + 8;
        #pragma unroll
        for (int bn = 0; bn < 4; bn++) {
            const int col = col0 + wn * 32 + bn * 8 + 2 * t;
            float v[4];
            #pragma unroll
            for (int i = 0; i < 4; i++) v[i] = acc[am][bn][i];
            if (EPI == 2) {
                #pragma unroll
                for (int i = 0; i < 4; i++) v[i] *= scale;
            } else {
                const float b0 = __ldg(&bias[col]);
                const float b1 = __ldg(&bias[col + 1]);
                v[0] += b0; v[1] += b1; v[2] += b0; v[3] += b1;
                if (EPI == 3) {
                    #pragma unroll
                    for (int i = 0; i < 4; i++) v[i] = gelu_exact(v[i]);
                }
            }
            if (EPI == 2) {
                *(float2*)(Cp + r0 * ldC + col) = make_float2(v[0], v[1]);
                *(float2*)(Cp + r1 * ldC + col) = make_float2(v[2], v[3]);
            } else if (vout) {
                // transposed V output (hi only): VT[b][e][s]
                const int e = col - 2 * EMBED;
                const long b0i = (r0 >> 10) * (long)EMBED * SEQ;
                const long s0 = r0 & 1023;
                const long b1i = (r1 >> 10) * (long)EMBED * SEQ;
                const long s1 = r1 & 1023;
                #pragma unroll
                for (int i = 0; i < 4; i++) {
                    const long o = ((i < 2) ? (b0i + s0) : (b1i + s1)) + (long)(e + (i & 1)) * SEQ;
                    VTh[o] = __float2half_rn(v[i]);
                }
            } else {
                fp16 a0 = __float2half_rn(v[0]), a1 = __float2half_rn(v[1]);
                fp16 a2 = __float2half_rn(v[2]), a3 = __float2half_rn(v[3]);
                *(ushort2*)(Hp + r0 * ldC + col) = make_ushort2(h2u(a0), h2u(a1));
                *(ushort2*)(Hp + r1 * ldC + col) = make_ushort2(h2u(a2), h2u(a3));
                *(ushort2*)(Lp + r0 * ldC + col) = make_ushort2(
                    h2u(__float2half_rn(v[0] - __half2float(a0))),
                    h2u(__float2half_rn(v[1] - __half2float(a1))));
                *(ushort2*)(Lp + r1 * ldC + col) = make_ushort2(
                    h2u(__float2half_rn(v[2] - __half2float(a2))),
                    h2u(__float2half_rn(v[3] - __half2float(a3))));
            }
        }
    }
}

// ============================ glue kernels ===================================
__global__ __launch_bounds__(256)
void split_kernel(const float* __restrict__ in, fp16* __restrict__ hi, fp16* __restrict__ lo, long n4)
{
    long i = (long)blockIdx.x * blockDim.x + threadIdx.x;
    if (i >= n4) return;
    float4 v = ((const float4*)in)[i];
    unsigned short h[4], l[4];
    float vv[4] = {v.x, v.y, v.z, v.w};
    #pragma unroll
    for (int j = 0; j < 4; j++) {
        fp16 hb = __float2half_rn(vv[j]);
        h[j] = __half_as_ushort(hb);
        l[j] = __half_as_ushort(__float2half_rn(vv[j] - __half2float(hb)));
    }
    ((uint2*)hi)[i] = *(uint2*)h;
    ((uint2*)lo)[i] = *(uint2*)l;
}

// One launch: transpose all 5 weights [R,C]->[C,R] fp16 (hi only) + bias concat.
__global__ __launch_bounds__(256)
void mega_wsplit(const float* __restrict__ Wq, const float* __restrict__ Wk,
                 const float* __restrict__ Wv, const float* __restrict__ W1,
                 const float* __restrict__ W2,
                 const float* __restrict__ bq, const float* __restrict__ bk,
                 const float* __restrict__ bv,
                 fp16* __restrict__ W1h, fp16* __restrict__ W2h,
                 float* __restrict__ bqkv)
{
    const int tflat = threadIdx.y * 32 + threadIdx.x;
    const int blk = blockIdx.x;
    if (blk == 6336) {
        for (int i = tflat; i < NQKV; i += 256)
            bqkv[i] = (i < EMBED) ? bq[i] : (i < 2 * EMBED) ? bk[i - EMBED] : bv[i - 2 * EMBED];
        return;
    }
    const float* in; fp16* hi;
    int R, C, bx, by;
    if (blk < 1728) {
        const int ww = blk / 576, loc = blk % 576;
        in = (ww == 0) ? Wq : (ww == 1) ? Wk : Wv;
        hi = g_Wqkvh + (long)ww * EMBED * EMBED;
        R = EMBED; C = EMBED; bx = loc % 24; by = loc / 24;
    } else if (blk < 4032) {
        const int loc = blk - 1728;
        in = W1; hi = W1h;
        R = EMBED; C = FF; bx = loc % 96; by = loc / 96;
    } else {
        const int loc = blk - 4032;
        in = W2; hi = W2h;
        R = FF; C = EMBED; bx = loc % 24; by = loc / 24;
    }
    __shared__ float tshr[32][33];
    const int tx = threadIdx.x, ty = threadIdx.y;
    const int c = bx * 32 + tx;
    const int r0 = by * 32;
    #pragma unroll
    for (int i = 0; i < 4; i++)
        tshr[ty + i * 8][tx] = in[(long)(r0 + ty + i * 8) * C + c];
    __syncthreads();
    const int co0 = bx * 32;
    #pragma unroll
    for (int i = 0; i < 4; i++) {
        float v = tshr[tx][ty + i * 8];
        long o = (long)(co0 + ty + i * 8) * R + r0 + tx;
        hi[o] = __float2half_rn(v);
    }
}

__global__ __launch_bounds__(256)
void softmax_kernel(float* __restrict__ S, fp16* __restrict__ Phi, fp16* __restrict__ Plo)
{
    float* row = S + (long)blockIdx.x * SEQ;
    const int tid = threadIdx.x;
    float v[4];
    float m = -1e30f;
    #pragma unroll
    for (int j = 0; j < 4; j++) { v[j] = row[tid + 256 * j]; m = fmaxf(m, v[j]); }
    __shared__ float red[8];
    #pragma unroll
    for (int o = 16; o > 0; o >>= 1) m = fmaxf(m, __shfl_xor_sync(0xffffffffu, m, o));
    if ((tid & 31) == 0) red[tid >> 5] = m;
    __syncthreads();
    m = red[0];
    #pragma unroll
    for (int i = 1; i < 8; i++) m = fmaxf(m, red[i]);
    float s = 0.0f;
    #pragma unroll
    for (int j = 0; j < 4; j++) { v[j] = __expf(v[j] - m); s += v[j]; }
    __syncthreads();
    #pragma unroll
    for (int o = 16; o > 0; o >>= 1) s += __shfl_xor_sync(0xffffffffu, s, o);
    if ((tid & 31) == 0) red[tid >> 5] = s;
    __syncthreads();
    s = 0.0f;
    #pragma unroll
    for (int i = 0; i < 8; i++) s += red[i];
    const float inv = 1.0f / s;
    fp16* ph = Phi + (long)blockIdx.x * SEQ;
    fp16* pl = Plo + (long)blockIdx.x * SEQ;
    #pragma unroll
    for (int j = 0; j < 4; j++) {
        float p = v[j] * inv;
        fp16 h = __float2half_rn(p);
        ph[tid + 256 * j] = h;
        pl[tid + 256 * j] = __float2half_rn(p - __half2float(h));
    }
}

// out = xin + LN(t0 (+t1) (+t2) (+bias)) * g + beta;  optional hi/lo split out.
template <int NT, bool HASB, bool SPLIT>
__global__ __launch_bounds__(256)
void ln_residual_kernel(const float* __restrict__ xin,
                        const float* __restrict__ t0, const float* __restrict__ t1,
                        const float* __restrict__ t2, const float* __restrict__ bvec,
                        const float* __restrict__ g, const float* __restrict__ beta,
                        float* __restrict__ out, fp16* __restrict__ ohi, fp16* __restrict__ olo)
{
    const long base = (long)blockIdx.x * EMBED;
    const int tid = threadIdx.x;
    float vv[3];
    #pragma unroll
    for (int j = 0; j < 3; j++) {
        const int o = tid + j * 256;
        float v = t0[base + o];
        if (NT >= 2) v += t1[base + o];
        if (NT >= 3) v += t2[base + o];
        if (HASB)    v += bvec[o];
        vv[j] = v;
    }
    float s = vv[0] + vv[1] + vv[2];
    float q = vv[0] * vv[0] + vv[1] * vv[1] + vv[2] * vv[2];
    __shared__ float rs[8], rq[8];
    #pragma unroll
    for (int o = 16; o > 0; o >>= 1) {
        s += __shfl_xor_sync(0xffffffffu, s, o);
        q += __shfl_xor_sync(0xffffffffu, q, o);
    }
    if ((tid & 31) == 0) { rs[tid >> 5] = s; rq[tid >> 5] = q; }
    __syncthreads();
    s = 0.0f; q = 0.0f;
    #pragma unroll
    for (int i = 0; i < 8; i++) { s += rs[i]; q += rq[i]; }
    const float mu  = s * (1.0f / EMBED);
    const float var = q * (1.0f / EMBED) - mu * mu;
    const float inv = rsqrtf(var + 1e-5f);
    #pragma unroll
    for (int j = 0; j < 3; j++) {
        const int o = tid + j * 256;
        float r = xin[base + o] + (vv[j] - mu) * inv * g[o] + beta[o];
        out[base + o] = r;
        if (SPLIT) {
            fp16 h = __float2half_rn(r);
            ohi[base + o] = h;
            olo[base + o] = __float2half_rn(r - __half2float(h));
        }
    }
}

// ============================ launcher =======================================
extern "C" void kernel_launch(void* const* d_in, const int* in_sizes, int n_in,
                              void* d_out, int out_size)
{
    const float* x     = (const float*)d_in[0];
    const float* Wq    = (const float*)d_in[1];
    const float* bq    = (const float*)d_in[2];
    const float* Wk    = (const float*)d_in[3];
    const float* bk    = (const float*)d_in[4];
    const float* Wv    = (const float*)d_in[5];
    const float* bv    = (const float*)d_in[6];
    const float* W1    = (const float*)d_in[7];
    const float* b1    = (const float*)d_in[8];
    const float* W2    = (const float*)d_in[9];
    const float* b2    = (const float*)d_in[10];
    const float* g1    = (const float*)d_in[11];
    const float* beta1 = (const float*)d_in[12];
    const float* g2    = (const float*)d_in[13];
    const float* beta2 = (const float*)d_in[14];
    float* out = (float*)d_out;

    fp16 *xhi, *xlo, *Wqkvh, *W1Th, *W2Th;
    fp16 *QKVh, *QKVl, *VTh, *Phi, *Plo, *x1hi, *x1lo, *hhi, *hlo;
    float *bqkv, *S, *attnP, *x1, *fP;
    cudaGetSymbolAddress((void**)&xhi, g_xhi);     cudaGetSymbolAddress((void**)&xlo, g_xlo);
    cudaGetSymbolAddress((void**)&Wqkvh, g_Wqkvh);
    cudaGetSymbolAddress((void**)&bqkv, g_bqkv);
    cudaGetSymbolAddress((void**)&W1Th, g_W1Th);
    cudaGetSymbolAddress((void**)&W2Th, g_W2Th);
    cudaGetSymbolAddress((void**)&QKVh, g_QKVh);   cudaGetSymbolAddress((void**)&QKVl, g_QKVl);
    cudaGetSymbolAddress((void**)&VTh, g_VTh);
    cudaGetSymbolAddress((void**)&S, g_S);
    cudaGetSymbolAddress((void**)&Phi, g_Phi);     cudaGetSymbolAddress((void**)&Plo, g_Plo);
    cudaGetSymbolAddress((void**)&attnP, g_attnP);
    cudaGetSymbolAddress((void**)&x1, g_x1);
    cudaGetSymbolAddress((void**)&x1hi, g_x1hi);   cudaGetSymbolAddress((void**)&x1lo, g_x1lo);
    cudaGetSymbolAddress((void**)&hhi, g_hhi);     cudaGetSymbolAddress((void**)&hlo, g_hlo);
    cudaGetSymbolAddress((void**)&fP, g_fP);

    cudaFuncSetAttribute((const void*)mma_gemm_big<1, true>,  cudaFuncAttributeMaxDynamicSharedMemorySize, BSMEM_TOTAL);
    cudaFuncSetAttribute((const void*)mma_gemm_big<2, false>, cudaFuncAttributeMaxDynamicSharedMemorySize, BSMEM_TOTAL);
    cudaFuncSetAttribute((const void*)mma_gemm_big<3, false>, cudaFuncAttributeMaxDynamicSharedMemorySize, BSMEM_TOTAL);

    const dim3 blk(256);
    const dim3 gblk(512);
    const dim3 tblk(32, 8);
    const float att_scale = 1.0f / sqrtf((float)EMBED);

    // 0: split x -> hi/lo
    split_kernel<<<(TOK * EMBED / 4 + 255) / 256, blk>>>(x, xhi, xlo, TOK * EMBED / 4);
    // 1: all weight transposes (hi only) + bias concat
    mega_wsplit<<<6337, tblk>>>(Wq, Wk, Wv, W1, W2, bq, bk, bv, W1Th, W2Th, bqkv);
    // 2: fused QKV = x @ [Wq|Wk|Wv] + bias; Q,K -> hi/lo, V -> VT hi (fused transpose)
    mma_gemm_big<1, true><<<dim3(NQKV / BT_N, TOK / BT_M, 1), gblk, BSMEM_TOTAL>>>(
        xhi, xlo, EMBED, 0, Wqkvh, EMBED, 0,
        nullptr, QKVh, QKVl, NQKV, 0, bqkv, 0.f, EMBED, 1, 0, VTh);
    // 3: scores = Q @ K^T * scale
    mma_gemm_big<2, false><<<dim3(SEQ / BT_N, SEQ / BT_M, BATCH), gblk, BSMEM_TOTAL>>>(
        QKVh, QKVl, NQKV, (long)SEQ * NQKV,
        QKVh + EMBED, NQKV, (long)SEQ * NQKV,
        S, nullptr, nullptr, SEQ, (long)SEQ * SEQ, nullptr, att_scale, EMBED, 1, 0, nullptr);
    // 4: softmax -> P hi/lo
    softmax_kernel<<<TOK, blk>>>(S, Phi, Plo);
    // 5: attn partials = P @ V, split-K=2
    mma_gemm_big<2, false><<<dim3(EMBED / BT_N, SEQ / BT_M, BATCH * 2), gblk, BSMEM_TOTAL>>>(
        Phi, Plo, SEQ, (long)SEQ * SEQ, VTh, SEQ, (long)EMBED * SEQ,
        attnP, nullptr, nullptr, EMBED, (long)SEQ * EMBED, nullptr, 1.0f, SEQ / 2,
        2, (long)TOK * EMBED, nullptr);
    // 6: x1 = x + LN(attn0 + attn1)  (+ split)
    ln_residual_kernel<2, false, true><<<TOK, blk>>>(
        x, attnP, attnP + (long)TOK * EMBED, nullptr, nullptr, g1, beta1, x1, x1hi, x1lo);
    // 7: h = gelu(x1 @ W1 + b1) -> hi/lo
    mma_gemm_big<3, false><<<dim3(FF / BT_N, TOK / BT_M, 1), gblk, BSMEM_TOTAL>>>(
        x1hi, x1lo, EMBED, 0, W1Th, EMBED, 0,
        nullptr, hhi, hlo, FF, 0, b1, 0.f, EMBED, 1, 0, nullptr);
    // 8: f partials = h @ W2, split-K=3
    mma_gemm_big<2, false><<<dim3(EMBED / BT_N, TOK / BT_M, 3), gblk, BSMEM_TOTAL>>>(
        hhi, hlo, FF, 0, W2Th, FF, 0,
        fP, nullptr, nullptr, EMBED, 0, nullptr, 1.0f, FF / 3, 3, (long)TOK * EMBED, nullptr);
    // 9: out = x1 + LN(f0+f1+f2 + b2)
    ln_residual_kernel<3, true, false><<<TOK, blk>>>(
        x1, fP, fP + (long)TOK * EMBED, fP + 2L * TOK * EMBED, b2, g2, beta2,
        out, nullptr, nullptr);
}

// round 11
// speedup vs baseline: 1.4510x; 1.4510x over previous
#include <cuda_runtime.h>
#include <cuda_fp16.h>
#include <math.h>
#include <stdint.h>

#define EMBED 768
#define FF    3072
#define BATCH 8
#define SEQ   1024
#define TOK   (BATCH * SEQ)   // 8192
#define NQKV  (3 * EMBED)     // 2304

typedef __half fp16;

// ============================ scratch buffers ================================
__device__ __align__(16) fp16  g_xhi[TOK * EMBED];
__device__ __align__(16) fp16  g_Wqkvh[(long)NQKV * EMBED];
__device__ __align__(16) float g_bqkv[NQKV];
__device__ __align__(16) fp16  g_W1Th[(long)FF * EMBED];
__device__ __align__(16) fp16  g_W2Th[(long)EMBED * FF];
__device__ __align__(16) fp16  g_QKVh[(long)TOK * NQKV], g_QKVl[(long)TOK * NQKV];
__device__ __align__(16) fp16  g_VTh[(long)BATCH * EMBED * SEQ];
__device__ __align__(16) float g_S[(long)BATCH * SEQ * SEQ];
__device__ __align__(16) fp16  g_Phi[(long)BATCH * SEQ * SEQ], g_Plo[(long)BATCH * SEQ * SEQ];
__device__ __align__(16) float g_attnP[2L * TOK * EMBED];
__device__ __align__(16) float g_x1[TOK * EMBED];
__device__ __align__(16) fp16  g_x1hi[TOK * EMBED];
__device__ __align__(16) fp16  g_hhi[(long)TOK * FF];
__device__ __align__(16) float g_fP[3L * TOK * EMBED];

// ============================ PTX helpers ====================================
__device__ __forceinline__ uint32_t smem_u32(const void* p) {
    uint32_t a;
    asm("{ .reg .u64 t; cvta.to.shared.u64 t, %1; cvt.u32.u64 %0, t; }" : "=r"(a) : "l"(p));
    return a;
}
__device__ __forceinline__ void cp16(uint32_t dst, const void* src) {
    asm volatile("cp.async.cg.shared.global [%0], [%1], 16;" :: "r"(dst), "l"(src));
}
#define CP_COMMIT() asm volatile("cp.async.commit_group;" ::: "memory")

__device__ __forceinline__ void ldm_x4(uint32_t* r, uint32_t addr) {
    asm volatile("ldmatrix.sync.aligned.m8n8.x4.shared.b16 {%0,%1,%2,%3}, [%4];"
                 : "=r"(r[0]), "=r"(r[1]), "=r"(r[2]), "=r"(r[3]) : "r"(addr));
}
__device__ __forceinline__ void mma16816(float* d, const uint32_t* a, uint32_t b0, uint32_t b1) {
    asm volatile(
        "mma.sync.aligned.m16n8k16.row.col.f32.f16.f16.f32 "
        "{%0,%1,%2,%3}, {%4,%5,%6,%7}, {%8,%9}, {%0,%1,%2,%3};"
        : "+f"(d[0]), "+f"(d[1]), "+f"(d[2]), "+f"(d[3])
        : "r"(a[0]), "r"(a[1]), "r"(a[2]), "r"(a[3]), "r"(b0), "r"(b1));
}
#define SWZ128(o) ((o) ^ (((o) >> 3) & 0x70))

__device__ __forceinline__ float gelu_exact(float v) {
    return 0.5f * v * (1.0f + erff(v * 0.7071067811865475f));
}
__device__ __forceinline__ ushort h2u(fp16 h) { return __half_as_ushort(h); }

// ============================ mma GEMM =======================================
// ALO=true : C = (Ahi+Alo) @ Bhi^T   (2-pass, stage 80K: Ahi32|Alo32|Bhi16)
// ALO=false: C =  Ahi      @ Bhi^T   (1-pass, stage 48K: Ahi32|Bhi16)
// Both K-major row-major. CTA 256x128, 256 threads (8 warps, warp tile 64x64),
// BK=64, 2 stages. blockIdx.z = batch*ksplit + split; K = per-split length.
// EPI: 1 bias->(hi,lo) | 2 scale->fp32 | 3 bias+gelu->(hi only)
// VOUT (with EPI=1): CTAs with col0>=1536 write transposed VT (hi only).
#define BT_M 256
#define BT_N 128
#define BK   64

template <int EPI, bool VOUT, bool ALO>
__global__ __launch_bounds__(256, 1)
void mma_gemm_big(const fp16* __restrict__ Ahi, const fp16* __restrict__ Alo, long ldA, long bsA,
                  const fp16* __restrict__ Bhi, long ldB, long bsB,
                  float* __restrict__ C, fp16* __restrict__ Chi, fp16* __restrict__ Clo,
                  long ldC, long bsC, const float* __restrict__ bias, float scale, int K,
                  int ksplit, long spStrideC, fp16* __restrict__ VTh)
{
    constexpr uint32_t STG  = ALO ? 81920u : 49152u;
    constexpr uint32_t BOFF = ALO ? 65536u : 32768u;

    extern __shared__ char smem[];
    const uint32_t sbase = smem_u32(smem);
    const int tid  = threadIdx.x;
    const int bz   = blockIdx.z;
    const int sp   = bz % ksplit;
    const int bt   = bz / ksplit;
    const long koff = (long)sp * K;
    const int row0 = blockIdx.y * BT_M;
    const int col0 = blockIdx.x * BT_N;

    const fp16* Ah = Ahi + (long)bt * bsA + koff;
    const fp16* Al = ALO ? (Alo + (long)bt * bsA + koff) : nullptr;
    const fp16* Bh = Bhi + (long)bt * bsB + koff;

    const int NC = K / BK;

    auto load_stage = [&](int buf, int k0) {
        const uint32_t sb = sbase + (uint32_t)buf * STG;
        #pragma unroll
        for (int i = 0; i < 8; i++) {            // A: 2048 granules per half
            const int g = tid + 256 * i;
            const int r = g >> 3, c = g & 7;
            const uint32_t off = SWZ128((uint32_t)(r * 128 + c * 16));
            const long ai = (long)(row0 + r) * ldA + k0 + c * 8;
            cp16(sb + off, Ah + ai);
            if (ALO) cp16(sb + 32768 + off, Al + ai);
        }
        #pragma unroll
        for (int i = 0; i < 4; i++) {            // B: 1024 granules (hi only)
            const int g = tid + 256 * i;
            const int r = g >> 3, c = g & 7;
            const uint32_t off = SWZ128((uint32_t)(r * 128 + c * 16));
            const long bi = (long)(col0 + r) * ldB + k0 + c * 8;
            cp16(sb + BOFF + off, Bh + bi);
        }
    };

    load_stage(0, 0);
    CP_COMMIT();
    if (NC > 1) { load_stage(1, BK); CP_COMMIT(); }

    const int w    = tid >> 5;
    const int lane = tid & 31;
    const int wm   = w & 3;            // rows wm*64
    const int wn   = w >> 2;           // cols wn*64
    const int q    = lane >> 3;
    const int r8   = lane & 7;

    float acc[4][8][4];
    #pragma unroll
    for (int i = 0; i < 4; i++)
        #pragma unroll
        for (int j = 0; j < 8; j++)
            #pragma unroll
            for (int v = 0; v < 4; v++) acc[i][j][v] = 0.0f;

    for (int c = 0; c < NC; c++) {
        if (c + 1 < NC) asm volatile("cp.async.wait_group 1;" ::: "memory");
        else            asm volatile("cp.async.wait_group 0;" ::: "memory");
        __syncthreads();

        const uint32_t sb = sbase + (uint32_t)(c & 1) * STG;
        #pragma unroll
        for (int ks = 0; ks < 4; ks++) {
            uint32_t bhf[4][4];
            #pragma unroll
            for (int p = 0; p < 4; p++) {
                const int nn = wn * 64 + p * 16 + (q >> 1) * 8 + r8;
                const int cc = 2 * ks + (q & 1);
                ldm_x4(bhf[p], sb + BOFF + SWZ128((uint32_t)(nn * 128 + cc * 16)));
            }
            #pragma unroll
            for (int am = 0; am < 4; am++) {
                uint32_t ah[4], al[4];
                const int rr = wm * 64 + am * 16 + (q & 1) * 8 + r8;
                const int cc = 2 * ks + (q >> 1);
                const uint32_t off = SWZ128((uint32_t)(rr * 128 + cc * 16));
                ldm_x4(ah, sb + off);
                if (ALO) ldm_x4(al, sb + 32768 + off);
                #pragma unroll
                for (int bn = 0; bn < 8; bn++) {
                    const int p = bn >> 1, hf = (bn & 1) * 2;
                    mma16816(acc[am][bn], ah, bhf[p][hf], bhf[p][hf + 1]);
                    if (ALO) mma16816(acc[am][bn], al, bhf[p][hf], bhf[p][hf + 1]);
                }
            }
        }
        __syncthreads();
        if (c + 2 < NC) {
            load_stage(c & 1, (c + 2) * BK);
            CP_COMMIT();
        }
    }

    // -------- epilogue --------
    const int gg = lane >> 2, t = lane & 3;
    float* Cp = (EPI == 2) ? C + (long)bt * bsC + (long)sp * spStrideC : nullptr;
    fp16* Hp  = (EPI == 1 || EPI == 3) ? Chi + (long)bt * bsC : nullptr;
    fp16* Lp  = (EPI == 1) ? Clo + (long)bt * bsC : nullptr;
    const bool vout = VOUT && (col0 >= 2 * EMBED);

    #pragma unroll
    for (int am = 0; am < 4; am++) {
        const long r0 = row0 + wm * 64 + am * 16 + gg;
        const long r1 = r0 + 8;
        #pragma unroll
        for (int bn = 0; bn < 8; bn++) {
            const int col = col0 + wn * 64 + bn * 8 + 2 * t;
            float v[4];
            #pragma unroll
            for (int i = 0; i < 4; i++) v[i] = acc[am][bn][i];
            if (EPI == 2) {
                #pragma unroll
                for (int i = 0; i < 4; i++) v[i] *= scale;
            } else {
                const float b0 = __ldg(&bias[col]);
                const float b1 = __ldg(&bias[col + 1]);
                v[0] += b0; v[1] += b1; v[2] += b0; v[3] += b1;
                if (EPI == 3) {
                    #pragma unroll
                    for (int i = 0; i < 4; i++) v[i] = gelu_exact(v[i]);
                }
            }
            if (EPI == 2) {
                *(float2*)(Cp + r0 * ldC + col) = make_float2(v[0], v[1]);
                *(float2*)(Cp + r1 * ldC + col) = make_float2(v[2], v[3]);
            } else if (vout) {
                // transposed V output (hi only): VT[b][e][s]
                const int e = col - 2 * EMBED;
                const long b0i = (r0 >> 10) * (long)EMBED * SEQ;
                const long s0 = r0 & 1023;
                const long b1i = (r1 >> 10) * (long)EMBED * SEQ;
                const long s1 = r1 & 1023;
                #pragma unroll
                for (int i = 0; i < 4; i++) {
                    const long o = ((i < 2) ? (b0i + s0) : (b1i + s1)) + (long)(e + (i & 1)) * SEQ;
                    VTh[o] = __float2half_rn(v[i]);
                }
            } else {
                fp16 a0 = __float2half_rn(v[0]), a1 = __float2half_rn(v[1]);
                fp16 a2 = __float2half_rn(v[2]), a3 = __float2half_rn(v[3]);
                *(ushort2*)(Hp + r0 * ldC + col) = make_ushort2(h2u(a0), h2u(a1));
                *(ushort2*)(Hp + r1 * ldC + col) = make_ushort2(h2u(a2), h2u(a3));
                if (EPI == 1) {
                    *(ushort2*)(Lp + r0 * ldC + col) = make_ushort2(
                        h2u(__float2half_rn(v[0] - __half2float(a0))),
                        h2u(__float2half_rn(v[1] - __half2float(a1))));
                    *(ushort2*)(Lp + r1 * ldC + col) = make_ushort2(
                        h2u(__float2half_rn(v[2] - __half2float(a2))),
                        h2u(__float2half_rn(v[3] - __half2float(a3))));
                }
            }
        }
    }
}

// ============================ glue kernels ===================================
__global__ __launch_bounds__(256)
void split_kernel(const float* __restrict__ in, fp16* __restrict__ hi, long n4)
{
    long i = (long)blockIdx.x * blockDim.x + threadIdx.x;
    if (i >= n4) return;
    float4 v = ((const float4*)in)[i];
    unsigned short h[4];
    float vv[4] = {v.x, v.y, v.z, v.w};
    #pragma unroll
    for (int j = 0; j < 4; j++) h[j] = __half_as_ushort(__float2half_rn(vv[j]));
    ((uint2*)hi)[i] = *(uint2*)h;
}

// One launch: transpose all 5 weights [R,C]->[C,R] fp16 (hi only) + bias concat.
__global__ __launch_bounds__(256)
void mega_wsplit(const float* __restrict__ Wq, const float* __restrict__ Wk,
                 const float* __restrict__ Wv, const float* __restrict__ W1,
                 const float* __restrict__ W2,
                 const float* __restrict__ bq, const float* __restrict__ bk,
                 const float* __restrict__ bv,
                 fp16* __restrict__ W1h, fp16* __restrict__ W2h,
                 float* __restrict__ bqkv)
{
    const int tflat = threadIdx.y * 32 + threadIdx.x;
    const int blk = blockIdx.x;
    if (blk == 6336) {
        for (int i = tflat; i < NQKV; i += 256)
            bqkv[i] = (i < EMBED) ? bq[i] : (i < 2 * EMBED) ? bk[i - EMBED] : bv[i - 2 * EMBED];
        return;
    }
    const float* in; fp16* hi;
    int R, C, bx, by;
    if (blk < 1728) {
        const int ww = blk / 576, loc = blk % 576;
        in = (ww == 0) ? Wq : (ww == 1) ? Wk : Wv;
        hi = g_Wqkvh + (long)ww * EMBED * EMBED;
        R = EMBED; C = EMBED; bx = loc % 24; by = loc / 24;
    } else if (blk < 4032) {
        const int loc = blk - 1728;
        in = W1; hi = W1h;
        R = EMBED; C = FF; bx = loc % 96; by = loc / 96;
    } else {
        const int loc = blk - 4032;
        in = W2; hi = W2h;
        R = FF; C = EMBED; bx = loc % 24; by = loc / 24;
    }
    __shared__ float tshr[32][33];
    const int tx = threadIdx.x, ty = threadIdx.y;
    const int c = bx * 32 + tx;
    const int r0 = by * 32;
    #pragma unroll
    for (int i = 0; i < 4; i++)
        tshr[ty + i * 8][tx] = in[(long)(r0 + ty + i * 8) * C + c];
    __syncthreads();
    const int co0 = bx * 32;
    #pragma unroll
    for (int i = 0; i < 4; i++) {
        float v = tshr[tx][ty + i * 8];
        long o = (long)(co0 + ty + i * 8) * R + r0 + tx;
        hi[o] = __float2half_rn(v);
    }
}

__global__ __launch_bounds__(256)
void softmax_kernel(float* __restrict__ S, fp16* __restrict__ Phi, fp16* __restrict__ Plo)
{
    float* row = S + (long)blockIdx.x * SEQ;
    const int tid = threadIdx.x;
    float v[4];
    float m = -1e30f;
    #pragma unroll
    for (int j = 0; j < 4; j++) { v[j] = row[tid + 256 * j]; m = fmaxf(m, v[j]); }
    __shared__ float red[8];
    #pragma unroll
    for (int o = 16; o > 0; o >>= 1) m = fmaxf(m, __shfl_xor_sync(0xffffffffu, m, o));
    if ((tid & 31) == 0) red[tid >> 5] = m;
    __syncthreads();
    m = red[0];
    #pragma unroll
    for (int i = 1; i < 8; i++) m = fmaxf(m, red[i]);
    float s = 0.0f;
    #pragma unroll
    for (int j = 0; j < 4; j++) { v[j] = __expf(v[j] - m); s += v[j]; }
    __syncthreads();
    #pragma unroll
    for (int o = 16; o > 0; o >>= 1) s += __shfl_xor_sync(0xffffffffu, s, o);
    if ((tid & 31) == 0) red[tid >> 5] = s;
    __syncthreads();
    s = 0.0f;
    #pragma unroll
    for (int i = 0; i < 8; i++) s += red[i];
    const float inv = 1.0f / s;
    fp16* ph = Phi + (long)blockIdx.x * SEQ;
    fp16* pl = Plo + (long)blockIdx.x * SEQ;
    #pragma unroll
    for (int j = 0; j < 4; j++) {
        float p = v[j] * inv;
        fp16 h = __float2half_rn(p);
        ph[tid + 256 * j] = h;
        pl[tid + 256 * j] = __float2half_rn(p - __half2float(h));
    }
}

// out = xin + LN(t0 (+t1) (+t2) (+bias)) * g + beta;  optional hi split out.
template <int NT, bool HASB, bool SPLIT>
__global__ __launch_bounds__(256)
void ln_residual_kernel(const float* __restrict__ xin,
                        const float* __restrict__ t0, const float* __restrict__ t1,
                        const float* __restrict__ t2, const float* __restrict__ bvec,
                        const float* __restrict__ g, const float* __restrict__ beta,
                        float* __restrict__ out, fp16* __restrict__ ohi)
{
    const long base = (long)blockIdx.x * EMBED;
    const int tid = threadIdx.x;
    float vv[3];
    #pragma unroll
    for (int j = 0; j < 3; j++) {
        const int o = tid + j * 256;
        float v = t0[base + o];
        if (NT >= 2) v += t1[base + o];
        if (NT >= 3) v += t2[base + o];
        if (HASB)    v += bvec[o];
        vv[j] = v;
    }
    float s = vv[0] + vv[1] + vv[2];
    float q = vv[0] * vv[0] + vv[1] * vv[1] + vv[2] * vv[2];
    __shared__ float rs[8], rq[8];
    #pragma unroll
    for (int o = 16; o > 0; o >>= 1) {
        s += __shfl_xor_sync(0xffffffffu, s, o);
        q += __shfl_xor_sync(0xffffffffu, q, o);
    }
    if ((tid & 31) == 0) { rs[tid >> 5] = s; rq[tid >> 5] = q; }
    __syncthreads();
    s = 0.0f; q = 0.0f;
    #pragma unroll
    for (int i = 0; i < 8; i++) { s += rs[i]; q += rq[i]; }
    const float mu  = s * (1.0f / EMBED);
    const float var = q * (1.0f / EMBED) - mu * mu;
    const float inv = rsqrtf(var + 1e-5f);
    #pragma unroll
    for (int j = 0; j < 3; j++) {
        const int o = tid + j * 256;
        float r = xin[base + o] + (vv[j] - mu) * inv * g[o] + beta[o];
        out[base + o] = r;
        if (SPLIT) ohi[base + o] = __float2half_rn(r);
    }
}

// ============================ launcher =======================================
extern "C" void kernel_launch(void* const* d_in, const int* in_sizes, int n_in,
                              void* d_out, int out_size)
{
    const float* x     = (const float*)d_in[0];
    const float* Wq    = (const float*)d_in[1];
    const float* bq    = (const float*)d_in[2];
    const float* Wk    = (const float*)d_in[3];
    const float* bk    = (const float*)d_in[4];
    const float* Wv    = (const float*)d_in[5];
    const float* bv    = (const float*)d_in[6];
    const float* W1    = (const float*)d_in[7];
    const float* b1    = (const float*)d_in[8];
    const float* W2    = (const float*)d_in[9];
    const float* b2    = (const float*)d_in[10];
    const float* g1    = (const float*)d_in[11];
    const float* beta1 = (const float*)d_in[12];
    const float* g2    = (const float*)d_in[13];
    const float* beta2 = (const float*)d_in[14];
    float* out = (float*)d_out;

    fp16 *xhi, *Wqkvh, *W1Th, *W2Th;
    fp16 *QKVh, *QKVl, *VTh, *Phi, *Plo, *x1hi, *hhi;
    float *bqkv, *S, *attnP, *x1, *fP;
    cudaGetSymbolAddress((void**)&xhi, g_xhi);
    cudaGetSymbolAddress((void**)&Wqkvh, g_Wqkvh);
    cudaGetSymbolAddress((void**)&bqkv, g_bqkv);
    cudaGetSymbolAddress((void**)&W1Th, g_W1Th);
    cudaGetSymbolAddress((void**)&W2Th, g_W2Th);
    cudaGetSymbolAddress((void**)&QKVh, g_QKVh);   cudaGetSymbolAddress((void**)&QKVl, g_QKVl);
    cudaGetSymbolAddress((void**)&VTh, g_VTh);
    cudaGetSymbolAddress((void**)&S, g_S);
    cudaGetSymbolAddress((void**)&Phi, g_Phi);     cudaGetSymbolAddress((void**)&Plo, g_Plo);
    cudaGetSymbolAddress((void**)&attnP, g_attnP);
    cudaGetSymbolAddress((void**)&x1, g_x1);
    cudaGetSymbolAddress((void**)&x1hi, g_x1hi);
    cudaGetSymbolAddress((void**)&hhi, g_hhi);
    cudaGetSymbolAddress((void**)&fP, g_fP);

    const int SM_2P = 2 * 81920;   // 2-pass stages
    const int SM_1P = 2 * 49152;   // 1-pass stages
    cudaFuncSetAttribute((const void*)mma_gemm_big<1, true,  false>, cudaFuncAttributeMaxDynamicSharedMemorySize, SM_1P);
    cudaFuncSetAttribute((const void*)mma_gemm_big<2, false, true>,  cudaFuncAttributeMaxDynamicSharedMemorySize, SM_2P);
    cudaFuncSetAttribute((const void*)mma_gemm_big<3, false, false>, cudaFuncAttributeMaxDynamicSharedMemorySize, SM_1P);
    cudaFuncSetAttribute((const void*)mma_gemm_big<2, false, false>, cudaFuncAttributeMaxDynamicSharedMemorySize, SM_1P);

    const dim3 blk(256);
    const dim3 tblk(32, 8);
    const float att_scale = 1.0f / sqrtf((float)EMBED);

    // 0: x -> fp16 hi
    split_kernel<<<(TOK * EMBED / 4 + 255) / 256, blk>>>(x, xhi, TOK * EMBED / 4);
    // 1: all weight transposes (fp16) + bias concat
    mega_wsplit<<<6337, tblk>>>(Wq, Wk, Wv, W1, W2, bq, bk, bv, W1Th, W2Th, bqkv);
    // 2: fused QKV (1-pass) = x @ [Wq|Wk|Wv] + bias; Q,K -> hi/lo, V -> VT hi
    mma_gemm_big<1, true, false><<<dim3(NQKV / BT_N, TOK / BT_M, 1), blk, SM_1P>>>(
        xhi, nullptr, EMBED, 0, Wqkvh, EMBED, 0,
        nullptr, QKVh, QKVl, NQKV, 0, bqkv, 0.f, EMBED, 1, 0, VTh);
    // 3: scores (2-pass) = Q @ K^T * scale
    mma_gemm_big<2, false, true><<<dim3(SEQ / BT_N, SEQ / BT_M, BATCH), blk, SM_2P>>>(
        QKVh, QKVl, NQKV, (long)SEQ * NQKV,
        QKVh + EMBED, NQKV, (long)SEQ * NQKV,
        S, nullptr, nullptr, SEQ, (long)SEQ * SEQ, nullptr, att_scale, EMBED, 1, 0, nullptr);
    // 4: softmax -> P hi/lo
    softmax_kernel<<<TOK, blk>>>(S, Phi, Plo);
    // 5: attn partials (2-pass) = P @ V, split-K=2
    mma_gemm_big<2, false, true><<<dim3(EMBED / BT_N, SEQ / BT_M, BATCH * 2), blk, SM_2P>>>(
        Phi, Plo, SEQ, (long)SEQ * SEQ, VTh, SEQ, (long)EMBED * SEQ,
        attnP, nullptr, nullptr, EMBED, (long)SEQ * EMBED, nullptr, 1.0f, SEQ / 2,
        2, (long)TOK * EMBED, nullptr);
    // 6: x1 = x + LN(attn0 + attn1)  (+ hi split)
    ln_residual_kernel<2, false, true><<<TOK, blk>>>(
        x, attnP, attnP + (long)TOK * EMBED, nullptr, nullptr, g1, beta1, x1, x1hi);
    // 7: h = gelu(x1 @ W1 + b1) (1-pass) -> hi
    mma_gemm_big<3, false, false><<<dim3(FF / BT_N, TOK / BT_M, 1), blk, SM_1P>>>(
        x1hi, nullptr, EMBED, 0, W1Th, EMBED, 0,
        nullptr, hhi, nullptr, FF, 0, b1, 0.f, EMBED, 1, 0, nullptr);
    // 8: f partials = h @ W2 (1-pass), split-K=3
    mma_gemm_big<2, false, false><<<dim3(EMBED / BT_N, TOK / BT_M, 3), blk, SM_1P>>>(
        hhi, nullptr, FF, 0, W2Th, FF, 0,
        fP, nullptr, nullptr, EMBED, 0, nullptr, 1.0f, FF / 3, 3, (long)TOK * EMBED, nullptr);
    // 9: out = x1 + LN(f0+f1+f2 + b2)
    ln_residual_kernel<3, true, false><<<TOK, blk>>>(
        x1, fP, fP + (long)TOK * EMBED, fP + 2L * TOK * EMBED, b2, g2, beta2,
        out, nullptr);
}

// round 12
// speedup vs baseline: 1.6594x; 1.1436x over previous
#include <cuda_runtime.h>
#include <cuda_fp16.h>
#include <math.h>
#include <stdint.h>

#define EMBED 768
#define FF    3072
#define BATCH 8
#define SEQ   1024
#define TOK   (BATCH * SEQ)   // 8192
#define NQKV  (3 * EMBED)     // 2304

typedef __half fp16;

// ============================ scratch buffers ================================
__device__ __align__(16) fp16  g_xhi[TOK * EMBED];
__device__ __align__(16) fp16  g_Wqkvh[(long)NQKV * EMBED];
__device__ __align__(16) float g_bqkv[NQKV];
__device__ __align__(16) fp16  g_W1Th[(long)FF * EMBED];
__device__ __align__(16) fp16  g_W2Th[(long)EMBED * FF];
__device__ __align__(16) fp16  g_QKVh[(long)TOK * NQKV];
__device__ __align__(16) fp16  g_VTh[(long)BATCH * EMBED * SEQ];
__device__ __align__(16) float g_S[(long)BATCH * SEQ * SEQ];
__device__ __align__(16) fp16  g_Phi[(long)BATCH * SEQ * SEQ];
__device__ __align__(16) float g_attnP[2L * TOK * EMBED];
__device__ __align__(16) float g_x1[TOK * EMBED];
__device__ __align__(16) fp16  g_x1hi[TOK * EMBED];
__device__ __align__(16) fp16  g_hhi[(long)TOK * FF];
__device__ __align__(16) float g_fP[3L * TOK * EMBED];

// ============================ PTX helpers ====================================
__device__ __forceinline__ uint32_t smem_u32(const void* p) {
    uint32_t a;
    asm("{ .reg .u64 t; cvta.to.shared.u64 t, %1; cvt.u32.u64 %0, t; }" : "=r"(a) : "l"(p));
    return a;
}
__device__ __forceinline__ void cp16(uint32_t dst, const void* src) {
    asm volatile("cp.async.cg.shared.global [%0], [%1], 16;" :: "r"(dst), "l"(src));
}
#define CP_COMMIT() asm volatile("cp.async.commit_group;" ::: "memory")

__device__ __forceinline__ void ldm_x4(uint32_t* r, uint32_t addr) {
    asm volatile("ldmatrix.sync.aligned.m8n8.x4.shared.b16 {%0,%1,%2,%3}, [%4];"
                 : "=r"(r[0]), "=r"(r[1]), "=r"(r[2]), "=r"(r[3]) : "r"(addr));
}
__device__ __forceinline__ void mma16816(float* d, const uint32_t* a, uint32_t b0, uint32_t b1) {
    asm volatile(
        "mma.sync.aligned.m16n8k16.row.col.f32.f16.f16.f32 "
        "{%0,%1,%2,%3}, {%4,%5,%6,%7}, {%8,%9}, {%0,%1,%2,%3};"
        : "+f"(d[0]), "+f"(d[1]), "+f"(d[2]), "+f"(d[3])
        : "r"(a[0]), "r"(a[1]), "r"(a[2]), "r"(a[3]), "r"(b0), "r"(b1));
}
#define SWZ128(o) ((o) ^ (((o) >> 3) & 0x70))

__device__ __forceinline__ float gelu_exact(float v) {
    return 0.5f * v * (1.0f + erff(v * 0.7071067811865475f));
}
__device__ __forceinline__ ushort h2u(fp16 h) { return __half_as_ushort(h); }

// ============================ mma GEMM =======================================
// ALO=true : C = (Ahi+Alo) @ Bhi^T   (2-pass, stage 80K: Ahi32|Alo32|Bhi16)
// ALO=false: C =  Ahi      @ Bhi^T   (1-pass, stage 48K: Ahi32|Bhi16)
// Both K-major row-major. CTA 256x128, 256 threads (8 warps, warp tile 64x64),
// BK=64, 2 stages. blockIdx.z = batch*ksplit + split; K = per-split length.
// EPI: 1 bias->hi | 2 scale->fp32 | 3 bias+gelu->hi
// VOUT (with EPI=1): CTAs with col0>=1536 write transposed VT (hi only).
#define BT_M 256
#define BT_N 128
#define BK   64

template <int EPI, bool VOUT, bool ALO>
__global__ __launch_bounds__(256, 1)
void mma_gemm_big(const fp16* __restrict__ Ahi, const fp16* __restrict__ Alo, long ldA, long bsA,
                  const fp16* __restrict__ Bhi, long ldB, long bsB,
                  float* __restrict__ C, fp16* __restrict__ Chi,
                  long ldC, long bsC, const float* __restrict__ bias, float scale, int K,
                  int ksplit, long spStrideC, fp16* __restrict__ VTh)
{
    constexpr uint32_t STG  = ALO ? 81920u : 49152u;
    constexpr uint32_t BOFF = ALO ? 65536u : 32768u;

    extern __shared__ char smem[];
    const uint32_t sbase = smem_u32(smem);
    const int tid  = threadIdx.x;
    const int bz   = blockIdx.z;
    const int sp   = bz % ksplit;
    const int bt   = bz / ksplit;
    const long koff = (long)sp * K;
    const int row0 = blockIdx.y * BT_M;
    const int col0 = blockIdx.x * BT_N;

    const fp16* Ah = Ahi + (long)bt * bsA + koff;
    const fp16* Al = ALO ? (Alo + (long)bt * bsA + koff) : nullptr;
    const fp16* Bh = Bhi + (long)bt * bsB + koff;

    const int NC = K / BK;

    auto load_stage = [&](int buf, int k0) {
        const uint32_t sb = sbase + (uint32_t)buf * STG;
        #pragma unroll
        for (int i = 0; i < 8; i++) {            // A: 2048 granules per half
            const int g = tid + 256 * i;
            const int r = g >> 3, c = g & 7;
            const uint32_t off = SWZ128((uint32_t)(r * 128 + c * 16));
            const long ai = (long)(row0 + r) * ldA + k0 + c * 8;
            cp16(sb + off, Ah + ai);
            if (ALO) cp16(sb + 32768 + off, Al + ai);
        }
        #pragma unroll
        for (int i = 0; i < 4; i++) {            // B: 1024 granules (hi only)
            const int g = tid + 256 * i;
            const int r = g >> 3, c = g & 7;
            const uint32_t off = SWZ128((uint32_t)(r * 128 + c * 16));
            const long bi = (long)(col0 + r) * ldB + k0 + c * 8;
            cp16(sb + BOFF + off, Bh + bi);
        }
    };

    load_stage(0, 0);
    CP_COMMIT();
    if (NC > 1) { load_stage(1, BK); CP_COMMIT(); }

    const int w    = tid >> 5;
    const int lane = tid & 31;
    const int wm   = w & 3;            // rows wm*64
    const int wn   = w >> 2;           // cols wn*64
    const int q    = lane >> 3;
    const int r8   = lane & 7;

    float acc[4][8][4];
    #pragma unroll
    for (int i = 0; i < 4; i++)
        #pragma unroll
        for (int j = 0; j < 8; j++)
            #pragma unroll
            for (int v = 0; v < 4; v++) acc[i][j][v] = 0.0f;

    for (int c = 0; c < NC; c++) {
        if (c + 1 < NC) asm volatile("cp.async.wait_group 1;" ::: "memory");
        else            asm volatile("cp.async.wait_group 0;" ::: "memory");
        __syncthreads();

        const uint32_t sb = sbase + (uint32_t)(c & 1) * STG;
        #pragma unroll
        for (int ks = 0; ks < 4; ks++) {
            uint32_t bhf[4][4];
            #pragma unroll
            for (int p = 0; p < 4; p++) {
                const int nn = wn * 64 + p * 16 + (q >> 1) * 8 + r8;
                const int cc = 2 * ks + (q & 1);
                ldm_x4(bhf[p], sb + BOFF + SWZ128((uint32_t)(nn * 128 + cc * 16)));
            }
            #pragma unroll
            for (int am = 0; am < 4; am++) {
                uint32_t ah[4], al[4];
                const int rr = wm * 64 + am * 16 + (q & 1) * 8 + r8;
                const int cc = 2 * ks + (q >> 1);
                const uint32_t off = SWZ128((uint32_t)(rr * 128 + cc * 16));
                ldm_x4(ah, sb + off);
                if (ALO) ldm_x4(al, sb + 32768 + off);
                #pragma unroll
                for (int bn = 0; bn < 8; bn++) {
                    const int p = bn >> 1, hf = (bn & 1) * 2;
                    mma16816(acc[am][bn], ah, bhf[p][hf], bhf[p][hf + 1]);
                    if (ALO) mma16816(acc[am][bn], al, bhf[p][hf], bhf[p][hf + 1]);
                }
            }
        }
        __syncthreads();
        if (c + 2 < NC) {
            load_stage(c & 1, (c + 2) * BK);
            CP_COMMIT();
        }
    }

    // -------- epilogue --------
    const int gg = lane >> 2, t = lane & 3;
    float* Cp = (EPI == 2) ? C + (long)bt * bsC + (long)sp * spStrideC : nullptr;
    fp16* Hp  = (EPI == 1 || EPI == 3) ? Chi + (long)bt * bsC : nullptr;
    const bool vout = VOUT && (col0 >= 2 * EMBED);

    #pragma unroll
    for (int am = 0; am < 4; am++) {
        const long r0 = row0 + wm * 64 + am * 16 + gg;
        const long r1 = r0 + 8;
        #pragma unroll
        for (int bn = 0; bn < 8; bn++) {
            const int col = col0 + wn * 64 + bn * 8 + 2 * t;
            float v[4];
            #pragma unroll
            for (int i = 0; i < 4; i++) v[i] = acc[am][bn][i];
            if (EPI == 2) {
                #pragma unroll
                for (int i = 0; i < 4; i++) v[i] *= scale;
            } else {
                const float b0 = __ldg(&bias[col]);
                const float b1 = __ldg(&bias[col + 1]);
                v[0] += b0; v[1] += b1; v[2] += b0; v[3] += b1;
                if (EPI == 3) {
                    #pragma unroll
                    for (int i = 0; i < 4; i++) v[i] = gelu_exact(v[i]);
                }
            }
            if (EPI == 2) {
                *(float2*)(Cp + r0 * ldC + col) = make_float2(v[0], v[1]);
                *(float2*)(Cp + r1 * ldC + col) = make_float2(v[2], v[3]);
            } else if (vout) {
                // transposed V output (hi only): VT[b][e][s]
                const int e = col - 2 * EMBED;
                const long b0i = (r0 >> 10) * (long)EMBED * SEQ;
                const long s0 = r0 & 1023;
                const long b1i = (r1 >> 10) * (long)EMBED * SEQ;
                const long s1 = r1 & 1023;
                #pragma unroll
                for (int i = 0; i < 4; i++) {
                    const long o = ((i < 2) ? (b0i + s0) : (b1i + s1)) + (long)(e + (i & 1)) * SEQ;
                    VTh[o] = __float2half_rn(v[i]);
                }
            } else {
                fp16 a0 = __float2half_rn(v[0]), a1 = __float2half_rn(v[1]);
                fp16 a2 = __float2half_rn(v[2]), a3 = __float2half_rn(v[3]);
                *(ushort2*)(Hp + r0 * ldC + col) = make_ushort2(h2u(a0), h2u(a1));
                *(ushort2*)(Hp + r1 * ldC + col) = make_ushort2(h2u(a2), h2u(a3));
            }
        }
    }
}

// ============================ glue kernels ===================================
__global__ __launch_bounds__(256)
void split_kernel(const float* __restrict__ in, fp16* __restrict__ hi, long n4)
{
    long i = (long)blockIdx.x * blockDim.x + threadIdx.x;
    if (i >= n4) return;
    float4 v = ((const float4*)in)[i];
    unsigned short h[4];
    float vv[4] = {v.x, v.y, v.z, v.w};
    #pragma unroll
    for (int j = 0; j < 4; j++) h[j] = __half_as_ushort(__float2half_rn(vv[j]));
    ((uint2*)hi)[i] = *(uint2*)h;
}

// One launch: transpose all 5 weights [R,C]->[C,R] fp16 + bias concat.
__global__ __launch_bounds__(256)
void mega_wsplit(const float* __restrict__ Wq, const float* __restrict__ Wk,
                 const float* __restrict__ Wv, const float* __restrict__ W1,
                 const float* __restrict__ W2,
                 const float* __restrict__ bq, const float* __restrict__ bk,
                 const float* __restrict__ bv,
                 fp16* __restrict__ W1h, fp16* __restrict__ W2h,
                 float* __restrict__ bqkv)
{
    const int tflat = threadIdx.y * 32 + threadIdx.x;
    const int blk = blockIdx.x;
    if (blk == 6336) {
        for (int i = tflat; i < NQKV; i += 256)
            bqkv[i] = (i < EMBED) ? bq[i] : (i < 2 * EMBED) ? bk[i - EMBED] : bv[i - 2 * EMBED];
        return;
    }
    const float* in; fp16* hi;
    int R, C, bx, by;
    if (blk < 1728) {
        const int ww = blk / 576, loc = blk % 576;
        in = (ww == 0) ? Wq : (ww == 1) ? Wk : Wv;
        hi = g_Wqkvh + (long)ww * EMBED * EMBED;
        R = EMBED; C = EMBED; bx = loc % 24; by = loc / 24;
    } else if (blk < 4032) {
        const int loc = blk - 1728;
        in = W1; hi = W1h;
        R = EMBED; C = FF; bx = loc % 96; by = loc / 96;
    } else {
        const int loc = blk - 4032;
        in = W2; hi = W2h;
        R = FF; C = EMBED; bx = loc % 24; by = loc / 24;
    }
    __shared__ float tshr[32][33];
    const int tx = threadIdx.x, ty = threadIdx.y;
    const int c = bx * 32 + tx;
    const int r0 = by * 32;
    #pragma unroll
    for (int i = 0; i < 4; i++)
        tshr[ty + i * 8][tx] = in[(long)(r0 + ty + i * 8) * C + c];
    __syncthreads();
    const int co0 = bx * 32;
    #pragma unroll
    for (int i = 0; i < 4; i++) {
        float v = tshr[tx][ty + i * 8];
        long o = (long)(co0 + ty + i * 8) * R + r0 + tx;
        hi[o] = __float2half_rn(v);
    }
}

__global__ __launch_bounds__(256)
void softmax_kernel(float* __restrict__ S, fp16* __restrict__ Phi)
{
    float* row = S + (long)blockIdx.x * SEQ;
    const int tid = threadIdx.x;
    float v[4];
    float m = -1e30f;
    #pragma unroll
    for (int j = 0; j < 4; j++) { v[j] = row[tid + 256 * j]; m = fmaxf(m, v[j]); }
    __shared__ float red[8];
    #pragma unroll
    for (int o = 16; o > 0; o >>= 1) m = fmaxf(m, __shfl_xor_sync(0xffffffffu, m, o));
    if ((tid & 31) == 0) red[tid >> 5] = m;
    __syncthreads();
    m = red[0];
    #pragma unroll
    for (int i = 1; i < 8; i++) m = fmaxf(m, red[i]);
    float s = 0.0f;
    #pragma unroll
    for (int j = 0; j < 4; j++) { v[j] = __expf(v[j] - m); s += v[j]; }
    __syncthreads();
    #pragma unroll
    for (int o = 16; o > 0; o >>= 1) s += __shfl_xor_sync(0xffffffffu, s, o);
    if ((tid & 31) == 0) red[tid >> 5] = s;
    __syncthreads();
    s = 0.0f;
    #pragma unroll
    for (int i = 0; i < 8; i++) s += red[i];
    const float inv = 1.0f / s;
    fp16* ph = Phi + (long)blockIdx.x * SEQ;
    #pragma unroll
    for (int j = 0; j < 4; j++)
        ph[tid + 256 * j] = __float2half_rn(v[j] * inv);
}

// out = xin + LN(t0 (+t1) (+t2) (+bias)) * g + beta;  optional hi split out.
template <int NT, bool HASB, bool SPLIT>
__global__ __launch_bounds__(256)
void ln_residual_kernel(const float* __restrict__ xin,
                        const float* __restrict__ t0, const float* __restrict__ t1,
                        const float* __restrict__ t2, const float* __restrict__ bvec,
                        const float* __restrict__ g, const float* __restrict__ beta,
                        float* __restrict__ out, fp16* __restrict__ ohi)
{
    const long base = (long)blockIdx.x * EMBED;
    const int tid = threadIdx.x;
    float vv[3];
    #pragma unroll
    for (int j = 0; j < 3; j++) {
        const int o = tid + j * 256;
        float v = t0[base + o];
        if (NT >= 2) v += t1[base + o];
        if (NT >= 3) v += t2[base + o];
        if (HASB)    v += bvec[o];
        vv[j] = v;
    }
    float s = vv[0] + vv[1] + vv[2];
    float q = vv[0] * vv[0] + vv[1] * vv[1] + vv[2] * vv[2];
    __shared__ float rs[8], rq[8];
    #pragma unroll
    for (int o = 16; o > 0; o >>= 1) {
        s += __shfl_xor_sync(0xffffffffu, s, o);
        q += __shfl_xor_sync(0xffffffffu, q, o);
    }
    if ((tid & 31) == 0) { rs[tid >> 5] = s; rq[tid >> 5] = q; }
    __syncthreads();
    s = 0.0f; q = 0.0f;
    #pragma unroll
    for (int i = 0; i < 8; i++) { s += rs[i]; q += rq[i]; }
    const float mu  = s * (1.0f / EMBED);
    const float var = q * (1.0f / EMBED) - mu * mu;
    const float inv = rsqrtf(var + 1e-5f);
    #pragma unroll
    for (int j = 0; j < 3; j++) {
        const int o = tid + j * 256;
        float r = xin[base + o] + (vv[j] - mu) * inv * g[o] + beta[o];
        out[base + o] = r;
        if (SPLIT) ohi[base + o] = __float2half_rn(r);
    }
}

// ============================ launcher =======================================
extern "C" void kernel_launch(void* const* d_in, const int* in_sizes, int n_in,
                              void* d_out, int out_size)
{
    const float* x     = (const float*)d_in[0];
    const float* Wq    = (const float*)d_in[1];
    const float* bq    = (const float*)d_in[2];
    const float* Wk    = (const float*)d_in[3];
    const float* bk    = (const float*)d_in[4];
    const float* Wv    = (const float*)d_in[5];
    const float* bv    = (const float*)d_in[6];
    const float* W1    = (const float*)d_in[7];
    const float* b1    = (const float*)d_in[8];
    const float* W2    = (const float*)d_in[9];
    const float* b2    = (const float*)d_in[10];
    const float* g1    = (const float*)d_in[11];
    const float* beta1 = (const float*)d_in[12];
    const float* g2    = (const float*)d_in[13];
    const float* beta2 = (const float*)d_in[14];
    float* out = (float*)d_out;

    fp16 *xhi, *Wqkvh, *W1Th, *W2Th;
    fp16 *QKVh, *VTh, *Phi, *x1hi, *hhi;
    float *bqkv, *S, *attnP, *x1, *fP;
    cudaGetSymbolAddress((void**)&xhi, g_xhi);
    cudaGetSymbolAddress((void**)&Wqkvh, g_Wqkvh);
    cudaGetSymbolAddress((void**)&bqkv, g_bqkv);
    cudaGetSymbolAddress((void**)&W1Th, g_W1Th);
    cudaGetSymbolAddress((void**)&W2Th, g_W2Th);
    cudaGetSymbolAddress((void**)&QKVh, g_QKVh);
    cudaGetSymbolAddress((void**)&VTh, g_VTh);
    cudaGetSymbolAddress((void**)&S, g_S);
    cudaGetSymbolAddress((void**)&Phi, g_Phi);
    cudaGetSymbolAddress((void**)&attnP, g_attnP);
    cudaGetSymbolAddress((void**)&x1, g_x1);
    cudaGetSymbolAddress((void**)&x1hi, g_x1hi);
    cudaGetSymbolAddress((void**)&hhi, g_hhi);
    cudaGetSymbolAddress((void**)&fP, g_fP);

    const int SM_1P = 2 * 49152;   // 1-pass stages
    cudaFuncSetAttribute((const void*)mma_gemm_big<1, true,  false>, cudaFuncAttributeMaxDynamicSharedMemorySize, SM_1P);
    cudaFuncSetAttribute((const void*)mma_gemm_big<2, false, false>, cudaFuncAttributeMaxDynamicSharedMemorySize, SM_1P);
    cudaFuncSetAttribute((const void*)mma_gemm_big<3, false, false>, cudaFuncAttributeMaxDynamicSharedMemorySize, SM_1P);

    const dim3 blk(256);
    const dim3 tblk(32, 8);
    const float att_scale = 1.0f / sqrtf((float)EMBED);

    // 0: x -> fp16
    split_kernel<<<(TOK * EMBED / 4 + 255) / 256, blk>>>(x, xhi, TOK * EMBED / 4);
    // 1: all weight transposes (fp16) + bias concat
    mega_wsplit<<<6337, tblk>>>(Wq, Wk, Wv, W1, W2, bq, bk, bv, W1Th, W2Th, bqkv);
    // 2: fused QKV (1-pass) = x @ [Wq|Wk|Wv] + bias; Q,K -> hi, V -> VT (fused transpose)
    mma_gemm_big<1, true, false><<<dim3(NQKV / BT_N, TOK / BT_M, 1), blk, SM_1P>>>(
        xhi, nullptr, EMBED, 0, Wqkvh, EMBED, 0,
        nullptr, QKVh, NQKV, 0, bqkv, 0.f, EMBED, 1, 0, VTh);
    // 3: scores (1-pass) = Q @ K^T * scale
    mma_gemm_big<2, false, false><<<dim3(SEQ / BT_N, SEQ / BT_M, BATCH), blk, SM_1P>>>(
        QKVh, nullptr, NQKV, (long)SEQ * NQKV,
        QKVh + EMBED, NQKV, (long)SEQ * NQKV,
        S, nullptr, SEQ, (long)SEQ * SEQ, nullptr, att_scale, EMBED, 1, 0, nullptr);
    // 4: softmax -> P hi
    softmax_kernel<<<TOK, blk>>>(S, Phi);
    // 5: attn partials (1-pass) = P @ V, split-K=2
    mma_gemm_big<2, false, false><<<dim3(EMBED / BT_N, SEQ / BT_M, BATCH * 2), blk, SM_1P>>>(
        Phi, nullptr, SEQ, (long)SEQ * SEQ, VTh, SEQ, (long)EMBED * SEQ,
        attnP, nullptr, EMBED, (long)SEQ * EMBED, nullptr, 1.0f, SEQ / 2,
        2, (long)TOK * EMBED, nullptr);
    // 6: x1 = x + LN(attn0 + attn1)  (+ hi split)
    ln_residual_kernel<2, false, true><<<TOK, blk>>>(
        x, attnP, attnP + (long)TOK * EMBED, nullptr, nullptr, g1, beta1, x1, x1hi);
    // 7: h = gelu(x1 @ W1 + b1) (1-pass) -> hi
    mma_gemm_big<3, false, false><<<dim3(FF / BT_N, TOK / BT_M, 1), blk, SM_1P>>>(
        x1hi, nullptr, EMBED, 0, W1Th, EMBED, 0,
        nullptr, hhi, FF, 0, b1, 0.f, EMBED, 1, 0, nullptr);
    // 8: f partials = h @ W2 (1-pass), split-K=3
    mma_gemm_big<2, false, false><<<dim3(EMBED / BT_N, TOK / BT_M, 3), blk, SM_1P>>>(
        hhi, nullptr, FF, 0, W2Th, FF, 0,
        fP, nullptr, EMBED, 0, nullptr, 1.0f, FF / 3, 3, (long)TOK * EMBED, nullptr);
    // 9: out = x1 + LN(f0+f1+f2 + b2)
    ln_residual_kernel<3, true, false><<<TOK, blk>>>(
        x1, fP, fP + (long)TOK * EMBED, fP + 2L * TOK * EMBED, b2, g2, beta2,
        out, nullptr);
}

// round 13
// speedup vs baseline: 1.6862x; 1.0162x over previous
#include <cuda_runtime.h>
#include <cuda_fp16.h>
#include <math.h>
#include <stdint.h>

#define EMBED 768
#define FF    3072
#define BATCH 8
#define SEQ   1024
#define TOK   (BATCH * SEQ)   // 8192
#define NQKV  (3 * EMBED)     // 2304

typedef __half fp16;

// ============================ scratch buffers ================================
__device__ __align__(16) fp16  g_xhi[TOK * EMBED];
__device__ __align__(16) fp16  g_Wqkvh[(long)NQKV * EMBED];
__device__ __align__(16) float g_bqkv[NQKV];
__device__ __align__(16) fp16  g_W1Th[(long)FF * EMBED];
__device__ __align__(16) fp16  g_W2Th[(long)EMBED * FF];
__device__ __align__(16) fp16  g_QKVh[(long)TOK * NQKV];
__device__ __align__(16) fp16  g_VTh[(long)BATCH * EMBED * SEQ];
__device__ __align__(16) float g_S[(long)BATCH * SEQ * SEQ];
__device__ __align__(16) fp16  g_Phi[(long)BATCH * SEQ * SEQ];
__device__ __align__(16) float g_attnP[2L * TOK * EMBED];
__device__ __align__(16) float g_x1[TOK * EMBED];
__device__ __align__(16) fp16  g_x1hi[TOK * EMBED];
__device__ __align__(16) fp16  g_hhi[(long)TOK * FF];
__device__ __align__(16) float g_fP[3L * TOK * EMBED];

// ============================ PTX helpers ====================================
__device__ __forceinline__ uint32_t smem_u32(const void* p) {
    uint32_t a;
    asm("{ .reg .u64 t; cvta.to.shared.u64 t, %1; cvt.u32.u64 %0, t; }" : "=r"(a) : "l"(p));
    return a;
}
__device__ __forceinline__ void cp16(uint32_t dst, const void* src) {
    asm volatile("cp.async.cg.shared.global [%0], [%1], 16;" :: "r"(dst), "l"(src));
}
#define CP_COMMIT() asm volatile("cp.async.commit_group;" ::: "memory")

__device__ __forceinline__ void ldm_x4(uint32_t* r, uint32_t addr) {
    asm volatile("ldmatrix.sync.aligned.m8n8.x4.shared.b16 {%0,%1,%2,%3}, [%4];"
                 : "=r"(r[0]), "=r"(r[1]), "=r"(r[2]), "=r"(r[3]) : "r"(addr));
}
__device__ __forceinline__ void mma16816(float* d, const uint32_t* a, uint32_t b0, uint32_t b1) {
    asm volatile(
        "mma.sync.aligned.m16n8k16.row.col.f32.f16.f16.f32 "
        "{%0,%1,%2,%3}, {%4,%5,%6,%7}, {%8,%9}, {%0,%1,%2,%3};"
        : "+f"(d[0]), "+f"(d[1]), "+f"(d[2]), "+f"(d[3])
        : "r"(a[0]), "r"(a[1]), "r"(a[2]), "r"(a[3]), "r"(b0), "r"(b1));
}
#define SWZ128(o) ((o) ^ (((o) >> 3) & 0x70))

__device__ __forceinline__ float gelu_exact(float v) {
    return 0.5f * v * (1.0f + erff(v * 0.7071067811865475f));
}
__device__ __forceinline__ ushort h2u(fp16 h) { return __half_as_ushort(h); }

// ============================ mma GEMM (1-pass fp16) =========================
// C[M,N] = Ahi[M,K] @ Bhi[N,K]^T  (both K-major row-major)
// CTA 256x128, 256 threads (8 warps, warp tile 64x64), BK=64, 3 stages x 48KB,
// single barrier per chunk (load c+2 issued right after it), explicit
// double-buffered ldmatrix frag prefetch.
// blockIdx.z = batch*ksplit + split; K = per-split length.
// EPI: 1 bias->hi | 2 scale->fp32 | 3 bias+gelu->hi
// VOUT (with EPI=1): CTAs with col0>=1536 write transposed VT instead.
#define BT_M 256
#define BT_N 128
#define BK   64
#define STG  49152u            // A 32K | B 16K
#define BOFF 32768u
#define SM_GEMM (3 * 49152)

template <int EPI, bool VOUT>
__global__ __launch_bounds__(256, 1)
void mma_gemm_big(const fp16* __restrict__ Ahi, long ldA, long bsA,
                  const fp16* __restrict__ Bhi, long ldB, long bsB,
                  float* __restrict__ C, fp16* __restrict__ Chi,
                  long ldC, long bsC, const float* __restrict__ bias, float scale, int K,
                  int ksplit, long spStrideC, fp16* __restrict__ VTh)
{
    extern __shared__ char smem[];
    const uint32_t sbase = smem_u32(smem);
    const int tid  = threadIdx.x;
    const int bz   = blockIdx.z;
    const int sp   = bz % ksplit;
    const int bt   = bz / ksplit;
    const long koff = (long)sp * K;
    const int row0 = blockIdx.y * BT_M;
    const int col0 = blockIdx.x * BT_N;

    const fp16* Ah = Ahi + (long)bt * bsA + koff;
    const fp16* Bh = Bhi + (long)bt * bsB + koff;

    const int NC = K / BK;

    auto load_stage = [&](int buf, int k0) {
        const uint32_t sb = sbase + (uint32_t)buf * STG;
        #pragma unroll
        for (int i = 0; i < 8; i++) {            // A: 2048 granules
            const int g = tid + 256 * i;
            const int r = g >> 3, c = g & 7;
            const uint32_t off = SWZ128((uint32_t)(r * 128 + c * 16));
            cp16(sb + off, Ah + (long)(row0 + r) * ldA + k0 + c * 8);
        }
        #pragma unroll
        for (int i = 0; i < 4; i++) {            // B: 1024 granules
            const int g = tid + 256 * i;
            const int r = g >> 3, c = g & 7;
            const uint32_t off = SWZ128((uint32_t)(r * 128 + c * 16));
            cp16(sb + BOFF + off, Bh + (long)(col0 + r) * ldB + k0 + c * 8);
        }
    };

    load_stage(0, 0);      CP_COMMIT();
    if (NC > 1) { load_stage(1, BK); CP_COMMIT(); }

    const int w    = tid >> 5;
    const int lane = tid & 31;
    const int wm   = w & 3;            // rows wm*64
    const int wn   = w >> 2;           // cols wn*64
    const int q    = lane >> 3;
    const int r8   = lane & 7;

    // fixed per-thread frag row/col bases
    const int bNN = wn * 64 + (q >> 1) * 8 + r8;   // + p*16
    const int bAR = wm * 64 + (q & 1) * 8 + r8;    // + am*16
    const int bAC = (q >> 1);                      // + 2*ks
    const int bBC = (q & 1);                       // + 2*ks

    float acc[4][8][4];
    #pragma unroll
    for (int i = 0; i < 4; i++)
        #pragma unroll
        for (int j = 0; j < 8; j++)
            #pragma unroll
            for (int v = 0; v < 4; v++) acc[i][j][v] = 0.0f;

    uint32_t bf[2][4][4];
    uint32_t af[2][4];

    for (int c = 0; c < NC; c++) {
        if (c + 1 < NC) asm volatile("cp.async.wait_group 1;" ::: "memory");
        else            asm volatile("cp.async.wait_group 0;" ::: "memory");
        __syncthreads();                          // single barrier per chunk
        if (c + 2 < NC) {
            load_stage((c + 2) % 3, (c + 2) * BK);   // buffer freed by chunk c-1
            CP_COMMIT();
        }

        const uint32_t sb  = sbase + (uint32_t)(c % 3) * STG;
        const uint32_t sbB = sb + BOFF;

        // preload ks=0 B frags and (ks=0, am=0) A frag
        #pragma unroll
        for (int p = 0; p < 4; p++)
            ldm_x4(bf[0][p], sbB + SWZ128((uint32_t)((bNN + p * 16) * 128 + bBC * 16)));
        ldm_x4(af[0], sb + SWZ128((uint32_t)(bAR * 128 + bAC * 16)));

        #pragma unroll
        for (int ks = 0; ks < 4; ks++) {
            const int bcur = ks & 1, bnxt = bcur ^ 1;
            if (ks < 3) {
                const int cc = 2 * (ks + 1) + bBC;
                #pragma unroll
                for (int p = 0; p < 4; p++)
                    ldm_x4(bf[bnxt][p], sbB + SWZ128((uint32_t)((bNN + p * 16) * 128 + cc * 16)));
            }
            #pragma unroll
            for (int am = 0; am < 4; am++) {
                const int acur = am & 1, anxt = acur ^ 1;
                if (am < 3) {
                    const int cc = 2 * ks + bAC;
                    ldm_x4(af[anxt], sb + SWZ128((uint32_t)((bAR + (am + 1) * 16) * 128 + cc * 16)));
                } else if (ks < 3) {
                    const int cc = 2 * (ks + 1) + bAC;
                    ldm_x4(af[anxt], sb + SWZ128((uint32_t)(bAR * 128 + cc * 16)));
                }
                #pragma unroll
                for (int bn = 0; bn < 8; bn++) {
                    const int p = bn >> 1, hf = (bn & 1) * 2;
                    mma16816(acc[am][bn], af[acur], bf[bcur][p][hf], bf[bcur][p][hf + 1]);
                }
            }
        }
    }

    // -------- epilogue --------
    const int gg = lane >> 2, t = lane & 3;
    float* Cp = (EPI == 2) ? C + (long)bt * bsC + (long)sp * spStrideC : nullptr;
    fp16* Hp  = (EPI == 1 || EPI == 3) ? Chi + (long)bt * bsC : nullptr;
    const bool vout = VOUT && (col0 >= 2 * EMBED);

    #pragma unroll
    for (int am = 0; am < 4; am++) {
        const long r0 = row0 + wm * 64 + am * 16 + gg;
        const long r1 = r0 + 8;
        #pragma unroll
        for (int bn = 0; bn < 8; bn++) {
            const int col = col0 + wn * 64 + bn * 8 + 2 * t;
            float v[4];
            #pragma unroll
            for (int i = 0; i < 4; i++) v[i] = acc[am][bn][i];
            if (EPI == 2) {
                #pragma unroll
                for (int i = 0; i < 4; i++) v[i] *= scale;
            } else {
                const float b0 = __ldg(&bias[col]);
                const float b1 = __ldg(&bias[col + 1]);
                v[0] += b0; v[1] += b1; v[2] += b0; v[3] += b1;
                if (EPI == 3) {
                    #pragma unroll
                    for (int i = 0; i < 4; i++) v[i] = gelu_exact(v[i]);
                }
            }
            if (EPI == 2) {
                *(float2*)(Cp + r0 * ldC + col) = make_float2(v[0], v[1]);
                *(float2*)(Cp + r1 * ldC + col) = make_float2(v[2], v[3]);
            } else if (vout) {
                // transposed V output: VT[b][e][s]
                const int e = col - 2 * EMBED;
                const long b0i = (r0 >> 10) * (long)EMBED * SEQ;
                const long s0 = r0 & 1023;
                const long b1i = (r1 >> 10) * (long)EMBED * SEQ;
                const long s1 = r1 & 1023;
                #pragma unroll
                for (int i = 0; i < 4; i++) {
                    const long o = ((i < 2) ? (b0i + s0) : (b1i + s1)) + (long)(e + (i & 1)) * SEQ;
                    VTh[o] = __float2half_rn(v[i]);
                }
            } else {
                fp16 a0 = __float2half_rn(v[0]), a1 = __float2half_rn(v[1]);
                fp16 a2 = __float2half_rn(v[2]), a3 = __float2half_rn(v[3]);
                *(ushort2*)(Hp + r0 * ldC + col) = make_ushort2(h2u(a0), h2u(a1));
                *(ushort2*)(Hp + r1 * ldC + col) = make_ushort2(h2u(a2), h2u(a3));
            }
        }
    }
}

// ============================ glue kernels ===================================
__global__ __launch_bounds__(256)
void split_kernel(const float* __restrict__ in, fp16* __restrict__ hi, long n4)
{
    long i = (long)blockIdx.x * blockDim.x + threadIdx.x;
    if (i >= n4) return;
    float4 v = ((const float4*)in)[i];
    unsigned short h[4];
    float vv[4] = {v.x, v.y, v.z, v.w};
    #pragma unroll
    for (int j = 0; j < 4; j++) h[j] = __half_as_ushort(__float2half_rn(vv[j]));
    ((uint2*)hi)[i] = *(uint2*)h;
}

// One launch: transpose all 5 weights [R,C]->[C,R] fp16 + bias concat.
__global__ __launch_bounds__(256)
void mega_wsplit(const float* __restrict__ Wq, const float* __restrict__ Wk,
                 const float* __restrict__ Wv, const float* __restrict__ W1,
                 const float* __restrict__ W2,
                 const float* __restrict__ bq, const float* __restrict__ bk,
                 const float* __restrict__ bv,
                 fp16* __restrict__ W1h, fp16* __restrict__ W2h,
                 float* __restrict__ bqkv)
{
    const int tflat = threadIdx.y * 32 + threadIdx.x;
    const int blk = blockIdx.x;
    if (blk == 6336) {
        for (int i = tflat; i < NQKV; i += 256)
            bqkv[i] = (i < EMBED) ? bq[i] : (i < 2 * EMBED) ? bk[i - EMBED] : bv[i - 2 * EMBED];
        return;
    }
    const float* in; fp16* hi;
    int R, C, bx, by;
    if (blk < 1728) {
        const int ww = blk / 576, loc = blk % 576;
        in = (ww == 0) ? Wq : (ww == 1) ? Wk : Wv;
        hi = g_Wqkvh + (long)ww * EMBED * EMBED;
        R = EMBED; C = EMBED; bx = loc % 24; by = loc / 24;
    } else if (blk < 4032) {
        const int loc = blk - 1728;
        in = W1; hi = W1h;
        R = EMBED; C = FF; bx = loc % 96; by = loc / 96;
    } else {
        const int loc = blk - 4032;
        in = W2; hi = W2h;
        R = FF; C = EMBED; bx = loc % 24; by = loc / 24;
    }
    __shared__ float tshr[32][33];
    const int tx = threadIdx.x, ty = threadIdx.y;
    const int c = bx * 32 + tx;
    const int r0 = by * 32;
    #pragma unroll
    for (int i = 0; i < 4; i++)
        tshr[ty + i * 8][tx] = in[(long)(r0 + ty + i * 8) * C + c];
    __syncthreads();
    const int co0 = bx * 32;
    #pragma unroll
    for (int i = 0; i < 4; i++) {
        float v = tshr[tx][ty + i * 8];
        long o = (long)(co0 + ty + i * 8) * R + r0 + tx;
        hi[o] = __float2half_rn(v);
    }
}

__global__ __launch_bounds__(256)
void softmax_kernel(float* __restrict__ S, fp16* __restrict__ Phi)
{
    float* row = S + (long)blockIdx.x * SEQ;
    const int tid = threadIdx.x;
    float v[4];
    float m = -1e30f;
    #pragma unroll
    for (int j = 0; j < 4; j++) { v[j] = row[tid + 256 * j]; m = fmaxf(m, v[j]); }
    __shared__ float red[8];
    #pragma unroll
    for (int o = 16; o > 0; o >>= 1) m = fmaxf(m, __shfl_xor_sync(0xffffffffu, m, o));
    if ((tid & 31) == 0) red[tid >> 5] = m;
    __syncthreads();
    m = red[0];
    #pragma unroll
    for (int i = 1; i < 8; i++) m = fmaxf(m, red[i]);
    float s = 0.0f;
    #pragma unroll
    for (int j = 0; j < 4; j++) { v[j] = __expf(v[j] - m); s += v[j]; }
    __syncthreads();
    #pragma unroll
    for (int o = 16; o > 0; o >>= 1) s += __shfl_xor_sync(0xffffffffu, s, o);
    if ((tid & 31) == 0) red[tid >> 5] = s;
    __syncthreads();
    s = 0.0f;
    #pragma unroll
    for (int i = 0; i < 8; i++) s += red[i];
    const float inv = 1.0f / s;
    fp16* ph = Phi + (long)blockIdx.x * SEQ;
    #pragma unroll
    for (int j = 0; j < 4; j++)
        ph[tid + 256 * j] = __float2half_rn(v[j] * inv);
}

// out = xin + LN(t0 (+t1) (+t2) (+bias)) * g + beta;  optional hi split out.
template <int NT, bool HASB, bool SPLIT>
__global__ __launch_bounds__(256)
void ln_residual_kernel(const float* __restrict__ xin,
                        const float* __restrict__ t0, const float* __restrict__ t1,
                        const float* __restrict__ t2, const float* __restrict__ bvec,
                        const float* __restrict__ g, const float* __restrict__ beta,
                        float* __restrict__ out, fp16* __restrict__ ohi)
{
    const long base = (long)blockIdx.x * EMBED;
    const int tid = threadIdx.x;
    float vv[3];
    #pragma unroll
    for (int j = 0; j < 3; j++) {
        const int o = tid + j * 256;
        float v = t0[base + o];
        if (NT >= 2) v += t1[base + o];
        if (NT >= 3) v += t2[base + o];
        if (HASB)    v += bvec[o];
        vv[j] = v;
    }
    float s = vv[0] + vv[1] + vv[2];
    float q = vv[0] * vv[0] + vv[1] * vv[1] + vv[2] * vv[2];
    __shared__ float rs[8], rq[8];
    #pragma unroll
    for (int o = 16; o > 0; o >>= 1) {
        s += __shfl_xor_sync(0xffffffffu, s, o);
        q += __shfl_xor_sync(0xffffffffu, q, o);
    }
    if ((tid & 31) == 0) { rs[tid >> 5] = s; rq[tid >> 5] = q; }
    __syncthreads();
    s = 0.0f; q = 0.0f;
    #pragma unroll
    for (int i = 0; i < 8; i++) { s += rs[i]; q += rq[i]; }
    const float mu  = s * (1.0f / EMBED);
    const float var = q * (1.0f / EMBED) - mu * mu;
    const float inv = rsqrtf(var + 1e-5f);
    #pragma unroll
    for (int j = 0; j < 3; j++) {
        const int o = tid + j * 256;
        float r = xin[base + o] + (vv[j] - mu) * inv * g[o] + beta[o];
        out[base + o] = r;
        if (SPLIT) ohi[base + o] = __float2half_rn(r);
    }
}

// ============================ launcher =======================================
extern "C" void kernel_launch(void* const* d_in, const int* in_sizes, int n_in,
                              void* d_out, int out_size)
{
    const float* x     = (const float*)d_in[0];
    const float* Wq    = (const float*)d_in[1];
    const float* bq    = (const float*)d_in[2];
    const float* Wk    = (const float*)d_in[3];
    const float* bk    = (const float*)d_in[4];
    const float* Wv    = (const float*)d_in[5];
    const float* bv    = (const float*)d_in[6];
    const float* W1    = (const float*)d_in[7];
    const float* b1    = (const float*)d_in[8];
    const float* W2    = (const float*)d_in[9];
    const float* b2    = (const float*)d_in[10];
    const float* g1    = (const float*)d_in[11];
    const float* beta1 = (const float*)d_in[12];
    const float* g2    = (const float*)d_in[13];
    const float* beta2 = (const float*)d_in[14];
    float* out = (float*)d_out;

    fp16 *xhi, *Wqkvh, *W1Th, *W2Th;
    fp16 *QKVh, *VTh, *Phi, *x1hi, *hhi;
    float *bqkv, *S, *attnP, *x1, *fP;
    cudaGetSymbolAddress((void**)&xhi, g_xhi);
    cudaGetSymbolAddress((void**)&Wqkvh, g_Wqkvh);
    cudaGetSymbolAddress((void**)&bqkv, g_bqkv);
    cudaGetSymbolAddress((void**)&W1Th, g_W1Th);
    cudaGetSymbolAddress((void**)&W2Th, g_W2Th);
    cudaGetSymbolAddress((void**)&QKVh, g_QKVh);
    cudaGetSymbolAddress((void**)&VTh, g_VTh);
    cudaGetSymbolAddress((void**)&S, g_S);
    cudaGetSymbolAddress((void**)&Phi, g_Phi);
    cudaGetSymbolAddress((void**)&attnP, g_attnP);
    cudaGetSymbolAddress((void**)&x1, g_x1);
    cudaGetSymbolAddress((void**)&x1hi, g_x1hi);
    cudaGetSymbolAddress((void**)&hhi, g_hhi);
    cudaGetSymbolAddress((void**)&fP, g_fP);

    cudaFuncSetAttribute((const void*)mma_gemm_big<1, true>,  cudaFuncAttributeMaxDynamicSharedMemorySize, SM_GEMM);
    cudaFuncSetAttribute((const void*)mma_gemm_big<2, false>, cudaFuncAttributeMaxDynamicSharedMemorySize, SM_GEMM);
    cudaFuncSetAttribute((const void*)mma_gemm_big<3, false>, cudaFuncAttributeMaxDynamicSharedMemorySize, SM_GEMM);

    const dim3 blk(256);
    const dim3 tblk(32, 8);
    const float att_scale = 1.0f / sqrtf((float)EMBED);

    // 0: x -> fp16
    split_kernel<<<(TOK * EMBED / 4 + 255) / 256, blk>>>(x, xhi, TOK * EMBED / 4);
    // 1: all weight transposes (fp16) + bias concat
    mega_wsplit<<<6337, tblk>>>(Wq, Wk, Wv, W1, W2, bq, bk, bv, W1Th, W2Th, bqkv);
    // 2: fused QKV = x @ [Wq|Wk|Wv] + bias; Q,K -> hi, V -> VT (fused transpose)
    mma_gemm_big<1, true><<<dim3(NQKV / BT_N, TOK / BT_M, 1), blk, SM_GEMM>>>(
        xhi, EMBED, 0, Wqkvh, EMBED, 0,
        nullptr, QKVh, NQKV, 0, bqkv, 0.f, EMBED, 1, 0, VTh);
    // 3: scores = Q @ K^T * scale
    mma_gemm_big<2, false><<<dim3(SEQ / BT_N, SEQ / BT_M, BATCH), blk, SM_GEMM>>>(
        QKVh, NQKV, (long)SEQ * NQKV,
        QKVh + EMBED, NQKV, (long)SEQ * NQKV,
        S, nullptr, SEQ, (long)SEQ * SEQ, nullptr, att_scale, EMBED, 1, 0, nullptr);
    // 4: softmax -> P
    softmax_kernel<<<TOK, blk>>>(S, Phi);
    // 5: attn partials = P @ V, split-K=2
    mma_gemm_big<2, false><<<dim3(EMBED / BT_N, SEQ / BT_M, BATCH * 2), blk, SM_GEMM>>>(
        Phi, SEQ, (long)SEQ * SEQ, VTh, SEQ, (long)EMBED * SEQ,
        attnP, nullptr, EMBED, (long)SEQ * EMBED, nullptr, 1.0f, SEQ / 2,
        2, (long)TOK * EMBED, nullptr);
    // 6: x1 = x + LN(attn0 + attn1)  (+ hi split)
    ln_residual_kernel<2, false, true><<<TOK, blk>>>(
        x, attnP, attnP + (long)TOK * EMBED, nullptr, nullptr, g1, beta1, x1, x1hi);
    // 7: h = gelu(x1 @ W1 + b1) -> hi
    mma_gemm_big<3, false><<<dim3(FF / BT_N, TOK / BT_M, 1), blk, SM_GEMM>>>(
        x1hi, EMBED, 0, W1Th, EMBED, 0,
        nullptr, hhi, FF, 0, b1, 0.f, EMBED, 1, 0, nullptr);
    // 8: f partials = h @ W2, split-K=3
    mma_gemm_big<2, false><<<dim3(EMBED / BT_N, TOK / BT_M, 3), blk, SM_GEMM>>>(
        hhi, FF, 0, W2Th, FF, 0,
        fP, nullptr, EMBED, 0, nullptr, 1.0f, FF / 3, 3, (long)TOK * EMBED, nullptr);
    // 9: out = x1 + LN(f0+f1+f2 + b2)
    ln_residual_kernel<3, true, false><<<TOK, blk>>>(
        x1, fP, fP + (long)TOK * EMBED, fP + 2L * TOK * EMBED, b2, g2, beta2,
        out, nullptr);
}

// round 14
// speedup vs baseline: 1.7941x; 1.0639x over previous
#include <cuda_runtime.h>
#include <cuda_fp16.h>
#include <math.h>
#include <stdint.h>

#define EMBED 768
#define FF    3072
#define BATCH 8
#define SEQ   1024
#define TOK   (BATCH * SEQ)   // 8192
#define NQKV  (3 * EMBED)     // 2304

typedef __half fp16;

// ============================ scratch buffers ================================
__device__ __align__(16) fp16  g_xhi[TOK * EMBED];
__device__ __align__(16) fp16  g_Wqkvh[(long)NQKV * EMBED];
__device__ __align__(16) float g_bqkv[NQKV];
__device__ __align__(16) fp16  g_W1Th[(long)FF * EMBED];
__device__ __align__(16) fp16  g_W2Th[(long)EMBED * FF];
__device__ __align__(16) fp16  g_QKVh[(long)TOK * NQKV];
__device__ __align__(16) fp16  g_VTh[(long)BATCH * EMBED * SEQ];
__device__ __align__(16) float g_S[(long)BATCH * SEQ * SEQ];
__device__ __align__(16) fp16  g_Phi[(long)BATCH * SEQ * SEQ];
__device__ __align__(16) float g_attnP[2L * TOK * EMBED];
__device__ __align__(16) float g_x1[TOK * EMBED];
__device__ __align__(16) fp16  g_x1hi[TOK * EMBED];
__device__ __align__(16) fp16  g_hhi[(long)TOK * FF];
__device__ __align__(16) float g_fP[3L * TOK * EMBED];

// ============================ PTX helpers ====================================
__device__ __forceinline__ uint32_t smem_u32(const void* p) {
    uint32_t a;
    asm("{ .reg .u64 t; cvta.to.shared.u64 t, %1; cvt.u32.u64 %0, t; }" : "=r"(a) : "l"(p));
    return a;
}
__device__ __forceinline__ void cp16(uint32_t dst, const void* src) {
    asm volatile("cp.async.cg.shared.global [%0], [%1], 16;" :: "r"(dst), "l"(src));
}
#define CP_COMMIT() asm volatile("cp.async.commit_group;" ::: "memory")

__device__ __forceinline__ void ldm_x4(uint32_t* r, uint32_t addr) {
    asm volatile("ldmatrix.sync.aligned.m8n8.x4.shared.b16 {%0,%1,%2,%3}, [%4];"
                 : "=r"(r[0]), "=r"(r[1]), "=r"(r[2]), "=r"(r[3]) : "r"(addr));
}
__device__ __forceinline__ void mma16816(float* d, const uint32_t* a, uint32_t b0, uint32_t b1) {
    asm volatile(
        "mma.sync.aligned.m16n8k16.row.col.f32.f16.f16.f32 "
        "{%0,%1,%2,%3}, {%4,%5,%6,%7}, {%8,%9}, {%0,%1,%2,%3};"
        : "+f"(d[0]), "+f"(d[1]), "+f"(d[2]), "+f"(d[3])
        : "r"(a[0]), "r"(a[1]), "r"(a[2]), "r"(a[3]), "r"(b0), "r"(b1));
}
#define SWZ128(o) ((o) ^ (((o) >> 3) & 0x70))

__device__ __forceinline__ float gelu_exact(float v) {
    return 0.5f * v * (1.0f + erff(v * 0.7071067811865475f));
}
__device__ __forceinline__ ushort h2u(fp16 h) { return __half_as_ushort(h); }

// ============================ mma GEMM (1-pass fp16, 2 CTA/SM) ===============
// C[M,N] = Ahi[M,K] @ Bhi[N,K]^T  (both K-major row-major)
// CTA 128x128, 256 threads (8 warps: 2M x 4N, warp tile 64x32), BK=64,
// 3 stages x 32KB (A 16K | B 16K) = 96KB -> 2 CTAs/SM.
// Single barrier per chunk; load c+2 issued right after it.
// blockIdx.z = batch*ksplit + split; K = per-split length.
// EPI: 1 bias->hi | 2 scale->fp32 | 3 bias+gelu->hi
// VOUT (with EPI=1): CTAs with col0>=1536 write transposed VT instead.
#define BT_M 128
#define BT_N 128
#define BK   64
#define STG  32768u            // A 16K | B 16K
#define BOFF 16384u
#define SM_GEMM (3 * 32768)

template <int EPI, bool VOUT>
__global__ __launch_bounds__(256, 2)
void mma_gemm_big(const fp16* __restrict__ Ahi, long ldA, long bsA,
                  const fp16* __restrict__ Bhi, long ldB, long bsB,
                  float* __restrict__ C, fp16* __restrict__ Chi,
                  long ldC, long bsC, const float* __restrict__ bias, float scale, int K,
                  int ksplit, long spStrideC, fp16* __restrict__ VTh)
{
    extern __shared__ char smem[];
    const uint32_t sbase = smem_u32(smem);
    const int tid  = threadIdx.x;
    const int bz   = blockIdx.z;
    const int sp   = bz % ksplit;
    const int bt   = bz / ksplit;
    const long koff = (long)sp * K;
    const int row0 = blockIdx.y * BT_M;
    const int col0 = blockIdx.x * BT_N;

    const fp16* Ah = Ahi + (long)bt * bsA + koff;
    const fp16* Bh = Bhi + (long)bt * bsB + koff;

    const int NC = K / BK;

    auto load_stage = [&](int buf, int k0) {
        const uint32_t sb = sbase + (uint32_t)buf * STG;
        #pragma unroll
        for (int i = 0; i < 4; i++) {            // A: 1024 granules
            const int g = tid + 256 * i;
            const int r = g >> 3, c = g & 7;
            const uint32_t off = SWZ128((uint32_t)(r * 128 + c * 16));
            cp16(sb + off, Ah + (long)(row0 + r) * ldA + k0 + c * 8);
        }
        #pragma unroll
        for (int i = 0; i < 4; i++) {            // B: 1024 granules
            const int g = tid + 256 * i;
            const int r = g >> 3, c = g & 7;
            const uint32_t off = SWZ128((uint32_t)(r * 128 + c * 16));
            cp16(sb + BOFF + off, Bh + (long)(col0 + r) * ldB + k0 + c * 8);
        }
    };

    load_stage(0, 0);      CP_COMMIT();
    if (NC > 1) { load_stage(1, BK); CP_COMMIT(); }

    const int w    = tid >> 5;
    const int lane = tid & 31;
    const int wm   = w & 1;            // rows wm*64
    const int wn   = w >> 1;           // cols wn*32
    const int q    = lane >> 3;
    const int r8   = lane & 7;

    // fixed per-thread frag row/col bases
    const int bNN = wn * 32 + (q >> 1) * 8 + r8;   // + p*16
    const int bAR = wm * 64 + (q & 1) * 8 + r8;    // + am*16
    const int bAC = (q >> 1);                      // + 2*ks
    const int bBC = (q & 1);                       // + 2*ks

    float acc[4][4][4];
    #pragma unroll
    for (int i = 0; i < 4; i++)
        #pragma unroll
        for (int j = 0; j < 4; j++)
            #pragma unroll
            for (int v = 0; v < 4; v++) acc[i][j][v] = 0.0f;

    for (int c = 0; c < NC; c++) {
        if (c + 1 < NC) asm volatile("cp.async.wait_group 1;" ::: "memory");
        else            asm volatile("cp.async.wait_group 0;" ::: "memory");
        __syncthreads();                          // single barrier per chunk
        if (c + 2 < NC) {
            load_stage((c + 2) % 3, (c + 2) * BK);   // buffer freed by chunk c-1
            CP_COMMIT();
        }

        const uint32_t sb  = sbase + (uint32_t)(c % 3) * STG;
        const uint32_t sbB = sb + BOFF;

        #pragma unroll
        for (int ks = 0; ks < 4; ks++) {
            uint32_t bf[2][4];
            #pragma unroll
            for (int p = 0; p < 2; p++)
                ldm_x4(bf[p], sbB + SWZ128((uint32_t)((bNN + p * 16) * 128 + (2 * ks + bBC) * 16)));
            #pragma unroll
            for (int am = 0; am < 4; am++) {
                uint32_t af[4];
                ldm_x4(af, sb + SWZ128((uint32_t)((bAR + am * 16) * 128 + (2 * ks + bAC) * 16)));
                #pragma unroll
                for (int bn = 0; bn < 4; bn++) {
                    const int p = bn >> 1, hf = (bn & 1) * 2;
                    mma16816(acc[am][bn], af, bf[p][hf], bf[p][hf + 1]);
                }
            }
        }
    }

    // -------- epilogue --------
    const int gg = lane >> 2, t = lane & 3;
    float* Cp = (EPI == 2) ? C + (long)bt * bsC + (long)sp * spStrideC : nullptr;
    fp16* Hp  = (EPI == 1 || EPI == 3) ? Chi + (long)bt * bsC : nullptr;
    const bool vout = VOUT && (col0 >= 2 * EMBED);

    #pragma unroll
    for (int am = 0; am < 4; am++) {
        const long r0 = row0 + wm * 64 + am * 16 + gg;
        const long r1 = r0 + 8;
        #pragma unroll
        for (int bn = 0; bn < 4; bn++) {
            const int col = col0 + wn * 32 + bn * 8 + 2 * t;
            float v[4];
            #pragma unroll
            for (int i = 0; i < 4; i++) v[i] = acc[am][bn][i];
            if (EPI == 2) {
                #pragma unroll
                for (int i = 0; i < 4; i++) v[i] *= scale;
            } else {
                const float b0 = __ldg(&bias[col]);
                const float b1 = __ldg(&bias[col + 1]);
                v[0] += b0; v[1] += b1; v[2] += b0; v[3] += b1;
                if (EPI == 3) {
                    #pragma unroll
                    for (int i = 0; i < 4; i++) v[i] = gelu_exact(v[i]);
                }
            }
            if (EPI == 2) {
                *(float2*)(Cp + r0 * ldC + col) = make_float2(v[0], v[1]);
                *(float2*)(Cp + r1 * ldC + col) = make_float2(v[2], v[3]);
            } else if (vout) {
                // transposed V output: VT[b][e][s]
                const int e = col - 2 * EMBED;
                const long b0i = (r0 >> 10) * (long)EMBED * SEQ;
                const long s0 = r0 & 1023;
                const long b1i = (r1 >> 10) * (long)EMBED * SEQ;
                const long s1 = r1 & 1023;
                #pragma unroll
                for (int i = 0; i < 4; i++) {
                    const long o = ((i < 2) ? (b0i + s0) : (b1i + s1)) + (long)(e + (i & 1)) * SEQ;
                    VTh[o] = __float2half_rn(v[i]);
                }
            } else {
                fp16 a0 = __float2half_rn(v[0]), a1 = __float2half_rn(v[1]);
                fp16 a2 = __float2half_rn(v[2]), a3 = __float2half_rn(v[3]);
                *(ushort2*)(Hp + r0 * ldC + col) = make_ushort2(h2u(a0), h2u(a1));
                *(ushort2*)(Hp + r1 * ldC + col) = make_ushort2(h2u(a2), h2u(a3));
            }
        }
    }
}

// ============================ glue kernels ===================================
__global__ __launch_bounds__(256)
void split_kernel(const float* __restrict__ in, fp16* __restrict__ hi, long n4)
{
    long i = (long)blockIdx.x * blockDim.x + threadIdx.x;
    if (i >= n4) return;
    float4 v = ((const float4*)in)[i];
    unsigned short h[4];
    float vv[4] = {v.x, v.y, v.z, v.w};
    #pragma unroll
    for (int j = 0; j < 4; j++) h[j] = __half_as_ushort(__float2half_rn(vv[j]));
    ((uint2*)hi)[i] = *(uint2*)h;
}

// One launch: transpose all 5 weights [R,C]->[C,R] fp16 + bias concat.
__global__ __launch_bounds__(256)
void mega_wsplit(const float* __restrict__ Wq, const float* __restrict__ Wk,
                 const float* __restrict__ Wv, const float* __restrict__ W1,
                 const float* __restrict__ W2,
                 const float* __restrict__ bq, const float* __restrict__ bk,
                 const float* __restrict__ bv,
                 fp16* __restrict__ W1h, fp16* __restrict__ W2h,
                 float* __restrict__ bqkv)
{
    const int tflat = threadIdx.y * 32 + threadIdx.x;
    const int blk = blockIdx.x;
    if (blk == 6336) {
        for (int i = tflat; i < NQKV; i += 256)
            bqkv[i] = (i < EMBED) ? bq[i] : (i < 2 * EMBED) ? bk[i - EMBED] : bv[i - 2 * EMBED];
        return;
    }
    const float* in; fp16* hi;
    int R, C, bx, by;
    if (blk < 1728) {
        const int ww = blk / 576, loc = blk % 576;
        in = (ww == 0) ? Wq : (ww == 1) ? Wk : Wv;
        hi = g_Wqkvh + (long)ww * EMBED * EMBED;
        R = EMBED; C = EMBED; bx = loc % 24; by = loc / 24;
    } else if (blk < 4032) {
        const int loc = blk - 1728;
        in = W1; hi = W1h;
        R = EMBED; C = FF; bx = loc % 96; by = loc / 96;
    } else {
        const int loc = blk - 4032;
        in = W2; hi = W2h;
        R = FF; C = EMBED; bx = loc % 24; by = loc / 24;
    }
    __shared__ float tshr[32][33];
    const int tx = threadIdx.x, ty = threadIdx.y;
    const int c = bx * 32 + tx;
    const int r0 = by * 32;
    #pragma unroll
    for (int i = 0; i < 4; i++)
        tshr[ty + i * 8][tx] = in[(long)(r0 + ty + i * 8) * C + c];
    __syncthreads();
    const int co0 = bx * 32;
    #pragma unroll
    for (int i = 0; i < 4; i++) {
        float v = tshr[tx][ty + i * 8];
        long o = (long)(co0 + ty + i * 8) * R + r0 + tx;
        hi[o] = __float2half_rn(v);
    }
}

__global__ __launch_bounds__(256)
void softmax_kernel(float* __restrict__ S, fp16* __restrict__ Phi)
{
    float* row = S + (long)blockIdx.x * SEQ;
    const int tid = threadIdx.x;
    float v[4];
    float m = -1e30f;
    #pragma unroll
    for (int j = 0; j < 4; j++) { v[j] = row[tid + 256 * j]; m = fmaxf(m, v[j]); }
    __shared__ float red[8];
    #pragma unroll
    for (int o = 16; o > 0; o >>= 1) m = fmaxf(m, __shfl_xor_sync(0xffffffffu, m, o));
    if ((tid & 31) == 0) red[tid >> 5] = m;
    __syncthreads();
    m = red[0];
    #pragma unroll
    for (int i = 1; i < 8; i++) m = fmaxf(m, red[i]);
    float s = 0.0f;
    #pragma unroll
    for (int j = 0; j < 4; j++) { v[j] = __expf(v[j] - m); s += v[j]; }
    __syncthreads();
    #pragma unroll
    for (int o = 16; o > 0; o >>= 1) s += __shfl_xor_sync(0xffffffffu, s, o);
    if ((tid & 31) == 0) red[tid >> 5] = s;
    __syncthreads();
    s = 0.0f;
    #pragma unroll
    for (int i = 0; i < 8; i++) s += red[i];
    const float inv = 1.0f / s;
    fp16* ph = Phi + (long)blockIdx.x * SEQ;
    #pragma unroll
    for (int j = 0; j < 4; j++)
        ph[tid + 256 * j] = __float2half_rn(v[j] * inv);
}

// out = xin + LN(t0 (+t1) (+t2) (+bias)) * g + beta;  optional hi split out.
template <int NT, bool HASB, bool SPLIT>
__global__ __launch_bounds__(256)
void ln_residual_kernel(const float* __restrict__ xin,
                        const float* __restrict__ t0, const float* __restrict__ t1,
                        const float* __restrict__ t2, const float* __restrict__ bvec,
                        const float* __restrict__ g, const float* __restrict__ beta,
                        float* __restrict__ out, fp16* __restrict__ ohi)
{
    const long base = (long)blockIdx.x * EMBED;
    const int tid = threadIdx.x;
    float vv[3];
    #pragma unroll
    for (int j = 0; j < 3; j++) {
        const int o = tid + j * 256;
        float v = t0[base + o];
        if (NT >= 2) v += t1[base + o];
        if (NT >= 3) v += t2[base + o];
        if (HASB)    v += bvec[o];
        vv[j] = v;
    }
    float s = vv[0] + vv[1] + vv[2];
    float q = vv[0] * vv[0] + vv[1] * vv[1] + vv[2] * vv[2];
    __shared__ float rs[8], rq[8];
    #pragma unroll
    for (int o = 16; o > 0; o >>= 1) {
        s += __shfl_xor_sync(0xffffffffu, s, o);
        q += __shfl_xor_sync(0xffffffffu, q, o);
    }
    if ((tid & 31) == 0) { rs[tid >> 5] = s; rq[tid >> 5] = q; }
    __syncthreads();
    s = 0.0f; q = 0.0f;
    #pragma unroll
    for (int i = 0; i < 8; i++) { s += rs[i]; q += rq[i]; }
    const float mu  = s * (1.0f / EMBED);
    const float var = q * (1.0f / EMBED) - mu * mu;
    const float inv = rsqrtf(var + 1e-5f);
    #pragma unroll
    for (int j = 0; j < 3; j++) {
        const int o = tid + j * 256;
        float r = xin[base + o] + (vv[j] - mu) * inv * g[o] + beta[o];
        out[base + o] = r;
        if (SPLIT) ohi[base + o] = __float2half_rn(r);
    }
}

// ============================ launcher =======================================
extern "C" void kernel_launch(void* const* d_in, const int* in_sizes, int n_in,
                              void* d_out, int out_size)
{
    const float* x     = (const float*)d_in[0];
    const float* Wq    = (const float*)d_in[1];
    const float* bq    = (const float*)d_in[2];
    const float* Wk    = (const float*)d_in[3];
    const float* bk    = (const float*)d_in[4];
    const float* Wv    = (const float*)d_in[5];
    const float* bv    = (const float*)d_in[6];
    const float* W1    = (const float*)d_in[7];
    const float* b1    = (const float*)d_in[8];
    const float* W2    = (const float*)d_in[9];
    const float* b2    = (const float*)d_in[10];
    const float* g1    = (const float*)d_in[11];
    const float* beta1 = (const float*)d_in[12];
    const float* g2    = (const float*)d_in[13];
    const float* beta2 = (const float*)d_in[14];
    float* out = (float*)d_out;

    fp16 *xhi, *Wqkvh, *W1Th, *W2Th;
    fp16 *QKVh, *VTh, *Phi, *x1hi, *hhi;
    float *bqkv, *S, *attnP, *x1, *fP;
    cudaGetSymbolAddress((void**)&xhi, g_xhi);
    cudaGetSymbolAddress((void**)&Wqkvh, g_Wqkvh);
    cudaGetSymbolAddress((void**)&bqkv, g_bqkv);
    cudaGetSymbolAddress((void**)&W1Th, g_W1Th);
    cudaGetSymbolAddress((void**)&W2Th, g_W2Th);
    cudaGetSymbolAddress((void**)&QKVh, g_QKVh);
    cudaGetSymbolAddress((void**)&VTh, g_VTh);
    cudaGetSymbolAddress((void**)&S, g_S);
    cudaGetSymbolAddress((void**)&Phi, g_Phi);
    cudaGetSymbolAddress((void**)&attnP, g_attnP);
    cudaGetSymbolAddress((void**)&x1, g_x1);
    cudaGetSymbolAddress((void**)&x1hi, g_x1hi);
    cudaGetSymbolAddress((void**)&hhi, g_hhi);
    cudaGetSymbolAddress((void**)&fP, g_fP);

    cudaFuncSetAttribute((const void*)mma_gemm_big<1, true>,  cudaFuncAttributeMaxDynamicSharedMemorySize, SM_GEMM);
    cudaFuncSetAttribute((const void*)mma_gemm_big<2, false>, cudaFuncAttributeMaxDynamicSharedMemorySize, SM_GEMM);
    cudaFuncSetAttribute((const void*)mma_gemm_big<3, false>, cudaFuncAttributeMaxDynamicSharedMemorySize, SM_GEMM);

    const dim3 blk(256);
    const dim3 tblk(32, 8);
    const float att_scale = 1.0f / sqrtf((float)EMBED);

    // 0: x -> fp16
    split_kernel<<<(TOK * EMBED / 4 + 255) / 256, blk>>>(x, xhi, TOK * EMBED / 4);
    // 1: all weight transposes (fp16) + bias concat
    mega_wsplit<<<6337, tblk>>>(Wq, Wk, Wv, W1, W2, bq, bk, bv, W1Th, W2Th, bqkv);
    // 2: fused QKV = x @ [Wq|Wk|Wv] + bias; Q,K -> hi, V -> VT (fused transpose)
    mma_gemm_big<1, true><<<dim3(NQKV / BT_N, TOK / BT_M, 1), blk, SM_GEMM>>>(
        xhi, EMBED, 0, Wqkvh, EMBED, 0,
        nullptr, QKVh, NQKV, 0, bqkv, 0.f, EMBED, 1, 0, VTh);
    // 3: scores = Q @ K^T * scale
    mma_gemm_big<2, false><<<dim3(SEQ / BT_N, SEQ / BT_M, BATCH), blk, SM_GEMM>>>(
        QKVh, NQKV, (long)SEQ * NQKV,
        QKVh + EMBED, NQKV, (long)SEQ * NQKV,
        S, nullptr, SEQ, (long)SEQ * SEQ, nullptr, att_scale, EMBED, 1, 0, nullptr);
    // 4: softmax -> P
    softmax_kernel<<<TOK, blk>>>(S, Phi);
    // 5: attn partials = P @ V, split-K=2
    mma_gemm_big<2, false><<<dim3(EMBED / BT_N, SEQ / BT_M, BATCH * 2), blk, SM_GEMM>>>(
        Phi, SEQ, (long)SEQ * SEQ, VTh, SEQ, (long)EMBED * SEQ,
        attnP, nullptr, EMBED, (long)SEQ * EMBED, nullptr, 1.0f, SEQ / 2,
        2, (long)TOK * EMBED, nullptr);
    // 6: x1 = x + LN(attn0 + attn1)  (+ hi split)
    ln_residual_kernel<2, false, true><<<TOK, blk>>>(
        x, attnP, attnP + (long)TOK * EMBED, nullptr, nullptr, g1, beta1, x1, x1hi);
    // 7: h = gelu(x1 @ W1 + b1) -> hi
    mma_gemm_big<3, false><<<dim3(FF / BT_N, TOK / BT_M, 1), blk, SM_GEMM>>>(
        x1hi, EMBED, 0, W1Th, EMBED, 0,
        nullptr, hhi, FF, 0, b1, 0.f, EMBED, 1, 0, nullptr);
    // 8: f partials = h @ W2, split-K=3
    mma_gemm_big<2, false><<<dim3(EMBED / BT_N, TOK / BT_M, 3), blk, SM_GEMM>>>(
        hhi, FF, 0, W2Th, FF, 0,
        fP, nullptr, EMBED, 0, nullptr, 1.0f, FF / 3, 3, (long)TOK * EMBED, nullptr);
    // 9: out = x1 + LN(f0+f1+f2 + b2)
    ln_residual_kernel<3, true, false><<<TOK, blk>>>(
        x1, fP, fP + (long)TOK * EMBED, fP + 2L * TOK * EMBED, b2, g2, beta2,
        out, nullptr);
}

// round 16
// speedup vs baseline: 1.8102x; 1.0090x over previous
#include <cuda_runtime.h>
#include <cuda_fp16.h>
#include <math.h>
#include <stdint.h>

#define EMBED 768
#define FF    3072
#define BATCH 8
#define SEQ   1024
#define TOK   (BATCH * SEQ)   // 8192
#define NQKV  (3 * EMBED)     // 2304

typedef __half fp16;

// ============================ scratch buffers ================================
__device__ __align__(16) fp16  g_xhi[TOK * EMBED];
__device__ __align__(16) fp16  g_Wqkvh[(long)NQKV * EMBED];
__device__ __align__(16) float g_bqkv[NQKV];
__device__ __align__(16) fp16  g_W1Th[(long)FF * EMBED];
__device__ __align__(16) fp16  g_W2Th[(long)EMBED * FF];
__device__ __align__(16) fp16  g_QKVh[(long)TOK * NQKV];
__device__ __align__(16) fp16  g_VTh[(long)BATCH * EMBED * SEQ];
__device__ __align__(16) fp16  g_Sh[(long)BATCH * SEQ * SEQ];      // fp16 scores
__device__ __align__(16) fp16  g_Phi[(long)BATCH * SEQ * SEQ];
__device__ __align__(16) float g_attnP[2L * TOK * EMBED];
__device__ __align__(16) float g_x1[TOK * EMBED];
__device__ __align__(16) fp16  g_x1hi[TOK * EMBED];
__device__ __align__(16) fp16  g_hhi[(long)TOK * FF];
__device__ __align__(16) float g_fP[3L * TOK * EMBED];

// ============================ PTX helpers ====================================
__device__ __forceinline__ uint32_t smem_u32(const void* p) {
    uint32_t a;
    asm("{ .reg .u64 t; cvta.to.shared.u64 t, %1; cvt.u32.u64 %0, t; }" : "=r"(a) : "l"(p));
    return a;
}
__device__ __forceinline__ void cp16(uint32_t dst, const void* src) {
    asm volatile("cp.async.cg.shared.global [%0], [%1], 16;" :: "r"(dst), "l"(src));
}
#define CP_COMMIT() asm volatile("cp.async.commit_group;" ::: "memory")

__device__ __forceinline__ void ldm_x4(uint32_t* r, uint32_t addr) {
    asm volatile("ldmatrix.sync.aligned.m8n8.x4.shared.b16 {%0,%1,%2,%3}, [%4];"
                 : "=r"(r[0]), "=r"(r[1]), "=r"(r[2]), "=r"(r[3]) : "r"(addr));
}
__device__ __forceinline__ void mma16816(float* d, const uint32_t* a, uint32_t b0, uint32_t b1) {
    asm volatile(
        "mma.sync.aligned.m16n8k16.row.col.f32.f16.f16.f32 "
        "{%0,%1,%2,%3}, {%4,%5,%6,%7}, {%8,%9}, {%0,%1,%2,%3};"
        : "+f"(d[0]), "+f"(d[1]), "+f"(d[2]), "+f"(d[3])
        : "r"(a[0]), "r"(a[1]), "r"(a[2]), "r"(a[3]), "r"(b0), "r"(b1));
}
#define SWZ128(o) ((o) ^ (((o) >> 3) & 0x70))

__device__ __forceinline__ float gelu_exact(float v) {
    return 0.5f * v * (1.0f + erff(v * 0.7071067811865475f));
}
__device__ __forceinline__ ushort h2u(fp16 h) { return __half_as_ushort(h); }

// ============================ mma GEMM (1-pass fp16, 2 CTA/SM) ===============
// C[M,N] = Ahi[M,K] @ Bhi[N,K]^T  (both K-major row-major)
// CTA 128x128, 256 threads (8 warps: 2M x 4N, warp tile 64x32), BK=64,
// 3 stages x 32KB = 96KB -> 2 CTAs/SM.
// Per chunk (R14 proven order): wait_group -> barrier -> issue c+2 -> compute.
// (wait_group is per-thread; the barrier AFTER it is what makes the tile
//  readable by all threads — do not reorder.)
// blockIdx.z = batch*ksplit + split; K = per-split length.
// EPI: 1 bias->hi | 2 scale->fp32 | 3 bias+gelu->hi | 4 scale->fp16
// VOUT (with EPI=1): CTAs with col0>=1536 write transposed VT instead.
#define BT_M 128
#define BT_N 128
#define BK   64
#define STG  32768u            // A 16K | B 16K
#define BOFF 16384u
#define SM_GEMM (3 * 32768)

template <int EPI, bool VOUT>
__global__ __launch_bounds__(256, 2)
void mma_gemm_big(const fp16* __restrict__ Ahi, long ldA, long bsA,
                  const fp16* __restrict__ Bhi, long ldB, long bsB,
                  float* __restrict__ C, fp16* __restrict__ Chi,
                  long ldC, long bsC, const float* __restrict__ bias, float scale, int K,
                  int ksplit, long spStrideC, fp16* __restrict__ VTh)
{
    extern __shared__ char smem[];
    const uint32_t sbase = smem_u32(smem);
    const int tid  = threadIdx.x;
    const int bz   = blockIdx.z;
    const int sp   = bz % ksplit;
    const int bt   = bz / ksplit;
    const long koff = (long)sp * K;
    const int row0 = blockIdx.y * BT_M;
    const int col0 = blockIdx.x * BT_N;

    const fp16* Ah = Ahi + (long)bt * bsA + koff;
    const fp16* Bh = Bhi + (long)bt * bsB + koff;

    const int NC = K / BK;

    auto load_stage = [&](int buf, int k0) {
        const uint32_t sb = sbase + (uint32_t)buf * STG;
        #pragma unroll
        for (int i = 0; i < 4; i++) {            // A: 1024 granules
            const int g = tid + 256 * i;
            const int r = g >> 3, c = g & 7;
            const uint32_t off = SWZ128((uint32_t)(r * 128 + c * 16));
            cp16(sb + off, Ah + (long)(row0 + r) * ldA + k0 + c * 8);
        }
        #pragma unroll
        for (int i = 0; i < 4; i++) {            // B: 1024 granules
            const int g = tid + 256 * i;
            const int r = g >> 3, c = g & 7;
            const uint32_t off = SWZ128((uint32_t)(r * 128 + c * 16));
            cp16(sb + BOFF + off, Bh + (long)(col0 + r) * ldB + k0 + c * 8);
        }
    };

    load_stage(0, 0);      CP_COMMIT();
    if (NC > 1) { load_stage(1, BK); CP_COMMIT(); }

    const int w    = tid >> 5;
    const int lane = tid & 31;
    const int wm   = w & 1;            // rows wm*64
    const int wn   = w >> 1;           // cols wn*32
    const int q    = lane >> 3;
    const int r8   = lane & 7;

    const int bNN = wn * 32 + (q >> 1) * 8 + r8;   // + p*16
    const int bAR = wm * 64 + (q & 1) * 8 + r8;    // + am*16
    const int bAC = (q >> 1);                      // + 2*ks
    const int bBC = (q & 1);                       // + 2*ks

    float acc[4][4][4];
    #pragma unroll
    for (int i = 0; i < 4; i++)
        #pragma unroll
        for (int j = 0; j < 4; j++)
            #pragma unroll
            for (int v = 0; v < 4; v++) acc[i][j][v] = 0.0f;

    for (int c = 0; c < NC; c++) {
        if (c + 1 < NC) asm volatile("cp.async.wait_group 1;" ::: "memory");
        else            asm volatile("cp.async.wait_group 0;" ::: "memory");
        __syncthreads();                          // all threads' group c landed
        if (c + 2 < NC) {
            load_stage((c + 2) % 3, (c + 2) * BK);   // buffer freed by chunk c-1
            CP_COMMIT();
        }

        const uint32_t sb  = sbase + (uint32_t)(c % 3) * STG;
        const uint32_t sbB = sb + BOFF;

        #pragma unroll
        for (int ks = 0; ks < 4; ks++) {
            uint32_t bf[2][4];
            #pragma unroll
            for (int p = 0; p < 2; p++)
                ldm_x4(bf[p], sbB + SWZ128((uint32_t)((bNN + p * 16) * 128 + (2 * ks + bBC) * 16)));
            #pragma unroll
            for (int am = 0; am < 4; am++) {
                uint32_t af[4];
                ldm_x4(af, sb + SWZ128((uint32_t)((bAR + am * 16) * 128 + (2 * ks + bAC) * 16)));
                #pragma unroll
                for (int bn = 0; bn < 4; bn++) {
                    const int p = bn >> 1, hf = (bn & 1) * 2;
                    mma16816(acc[am][bn], af, bf[p][hf], bf[p][hf + 1]);
                }
            }
        }
    }

    // -------- epilogue --------
    const int gg = lane >> 2, t = lane & 3;
    float* Cp = (EPI == 2) ? C + (long)bt * bsC + (long)sp * spStrideC : nullptr;
    fp16* Hp  = (EPI == 1 || EPI == 3 || EPI == 4) ? Chi + (long)bt * bsC : nullptr;
    const bool vout = VOUT && (col0 >= 2 * EMBED);

    #pragma unroll
    for (int am = 0; am < 4; am++) {
        const long r0 = row0 + wm * 64 + am * 16 + gg;
        const long r1 = r0 + 8;
        #pragma unroll
        for (int bn = 0; bn < 4; bn++) {
            const int col = col0 + wn * 32 + bn * 8 + 2 * t;
            float v[4];
            #pragma unroll
            for (int i = 0; i < 4; i++) v[i] = acc[am][bn][i];
            if (EPI == 2 || EPI == 4) {
                #pragma unroll
                for (int i = 0; i < 4; i++) v[i] *= scale;
            } else {
                const float b0 = __ldg(&bias[col]);
                const float b1 = __ldg(&bias[col + 1]);
                v[0] += b0; v[1] += b1; v[2] += b0; v[3] += b1;
                if (EPI == 3) {
                    #pragma unroll
                    for (int i = 0; i < 4; i++) v[i] = gelu_exact(v[i]);
                }
            }
            if (EPI == 2) {
                *(float2*)(Cp + r0 * ldC + col) = make_float2(v[0], v[1]);
                *(float2*)(Cp + r1 * ldC + col) = make_float2(v[2], v[3]);
            } else if (vout) {
                const int e = col - 2 * EMBED;
                const long b0i = (r0 >> 10) * (long)EMBED * SEQ;
                const long s0 = r0 & 1023;
                const long b1i = (r1 >> 10) * (long)EMBED * SEQ;
                const long s1 = r1 & 1023;
                #pragma unroll
                for (int i = 0; i < 4; i++) {
                    const long o = ((i < 2) ? (b0i + s0) : (b1i + s1)) + (long)(e + (i & 1)) * SEQ;
                    VTh[o] = __float2half_rn(v[i]);
                }
            } else {
                fp16 a0 = __float2half_rn(v[0]), a1 = __float2half_rn(v[1]);
                fp16 a2 = __float2half_rn(v[2]), a3 = __float2half_rn(v[3]);
                *(ushort2*)(Hp + r0 * ldC + col) = make_ushort2(h2u(a0), h2u(a1));
                *(ushort2*)(Hp + r1 * ldC + col) = make_ushort2(h2u(a2), h2u(a3));
            }
        }
    }
}

// ============================ glue kernels ===================================
// One launch: transpose all 5 weights [R,C]->[C,R] fp16, bias concat,
// AND x -> fp16 conversion (blocks 6337..12480).
__global__ __launch_bounds__(256)
void mega_wsplit(const float* __restrict__ Wq, const float* __restrict__ Wk,
                 const float* __restrict__ Wv, const float* __restrict__ W1,
                 const float* __restrict__ W2, const float* __restrict__ x,
                 const float* __restrict__ bq, const float* __restrict__ bk,
                 const float* __restrict__ bv,
                 fp16* __restrict__ W1h, fp16* __restrict__ W2h,
                 fp16* __restrict__ xhi, float* __restrict__ bqkv)
{
    const int tflat = threadIdx.y * 32 + threadIdx.x;
    const int blk = blockIdx.x;
    if (blk >= 6337) {                           // x conversion: 6144 blocks
        const long i4 = (long)(blk - 6337) * 256 + tflat;   // float4 index
        float4 v = ((const float4*)x)[i4];
        unsigned short h[4];
        h[0] = __half_as_ushort(__float2half_rn(v.x));
        h[1] = __half_as_ushort(__float2half_rn(v.y));
        h[2] = __half_as_ushort(__float2half_rn(v.z));
        h[3] = __half_as_ushort(__float2half_rn(v.w));
        ((uint2*)xhi)[i4] = *(uint2*)h;
        return;
    }
    if (blk == 6336) {
        for (int i = tflat; i < NQKV; i += 256)
            bqkv[i] = (i < EMBED) ? bq[i] : (i < 2 * EMBED) ? bk[i - EMBED] : bv[i - 2 * EMBED];
        return;
    }
    const float* in; fp16* hi;
    int R, C, bx, by;
    if (blk < 1728) {
        const int ww = blk / 576, loc = blk % 576;
        in = (ww == 0) ? Wq : (ww == 1) ? Wk : Wv;
        hi = g_Wqkvh + (long)ww * EMBED * EMBED;
        R = EMBED; C = EMBED; bx = loc % 24; by = loc / 24;
    } else if (blk < 4032) {
        const int loc = blk - 1728;
        in = W1; hi = W1h;
        R = EMBED; C = FF; bx = loc % 96; by = loc / 96;
    } else {
        const int loc = blk - 4032;
        in = W2; hi = W2h;
        R = FF; C = EMBED; bx = loc % 24; by = loc / 24;
    }
    __shared__ float tshr[32][33];
    const int tx = threadIdx.x, ty = threadIdx.y;
    const int c = bx * 32 + tx;
    const int r0 = by * 32;
    #pragma unroll
    for (int i = 0; i < 4; i++)
        tshr[ty + i * 8][tx] = in[(long)(r0 + ty + i * 8) * C + c];
    __syncthreads();
    const int co0 = bx * 32;
    #pragma unroll
    for (int i = 0; i < 4; i++) {
        float v = tshr[tx][ty + i * 8];
        long o = (long)(co0 + ty + i * 8) * R + r0 + tx;
        hi[o] = __float2half_rn(v);
    }
}

__global__ __launch_bounds__(256)
void softmax_kernel(const fp16* __restrict__ S, fp16* __restrict__ Phi)
{
    const fp16* row = S + (long)blockIdx.x * SEQ;
    const int tid = threadIdx.x;
    float v[4];
    float m = -1e30f;
    #pragma unroll
    for (int j = 0; j < 4; j++) { v[j] = __half2float(row[tid + 256 * j]); m = fmaxf(m, v[j]); }
    __shared__ float red[8];
    #pragma unroll
    for (int o = 16; o > 0; o >>= 1) m = fmaxf(m, __shfl_xor_sync(0xffffffffu, m, o));
    if ((tid & 31) == 0) red[tid >> 5] = m;
    __syncthreads();
    m = red[0];
    #pragma unroll
    for (int i = 1; i < 8; i++) m = fmaxf(m, red[i]);
    float s = 0.0f;
    #pragma unroll
    for (int j = 0; j < 4; j++) { v[j] = __expf(v[j] - m); s += v[j]; }
    __syncthreads();
    #pragma unroll
    for (int o = 16; o > 0; o >>= 1) s += __shfl_xor_sync(0xffffffffu, s, o);
    if ((tid & 31) == 0) red[tid >> 5] = s;
    __syncthreads();
    s = 0.0f;
    #pragma unroll
    for (int i = 0; i < 8; i++) s += red[i];
    const float inv = 1.0f / s;
    fp16* ph = Phi + (long)blockIdx.x * SEQ;
    #pragma unroll
    for (int j = 0; j < 4; j++)
        ph[tid + 256 * j] = __float2half_rn(v[j] * inv);
}

// out = xin + LN(t0 (+t1) (+t2) (+bias)) * g + beta;  optional hi split out.
template <int NT, bool HASB, bool SPLIT>
__global__ __launch_bounds__(256)
void ln_residual_kernel(const float* __restrict__ xin,
                        const float* __restrict__ t0, const float* __restrict__ t1,
                        const float* __restrict__ t2, const float* __restrict__ bvec,
                        const float* __restrict__ g, const float* __restrict__ beta,
                        float* __restrict__ out, fp16* __restrict__ ohi)
{
    const long base = (long)blockIdx.x * EMBED;
    const int tid = threadIdx.x;
    float vv[3];
    #pragma unroll
    for (int j = 0; j < 3; j++) {
        const int o = tid + j * 256;
        float v = t0[base + o];
        if (NT >= 2) v += t1[base + o];
        if (NT >= 3) v += t2[base + o];
        if (HASB)    v += bvec[o];
        vv[j] = v;
    }
    float s = vv[0] + vv[1] + vv[2];
    float q = vv[0] * vv[0] + vv[1] * vv[1] + vv[2] * vv[2];
    __shared__ float rs[8], rq[8];
    #pragma unroll
    for (int o = 16; o > 0; o >>= 1) {
        s += __shfl_xor_sync(0xffffffffu, s, o);
        q += __shfl_xor_sync(0xffffffffu, q, o);
    }
    if ((tid & 31) == 0) { rs[tid >> 5] = s; rq[tid >> 5] = q; }
    __syncthreads();
    s = 0.0f; q = 0.0f;
    #pragma unroll
    for (int i = 0; i < 8; i++) { s += rs[i]; q += rq[i]; }
    const float mu  = s * (1.0f / EMBED);
    const float var = q * (1.0f / EMBED) - mu * mu;
    const float inv = rsqrtf(var + 1e-5f);
    #pragma unroll
    for (int j = 0; j < 3; j++) {
        const int o = tid + j * 256;
        float r = xin[base + o] + (vv[j] - mu) * inv * g[o] + beta[o];
        out[base + o] = r;
        if (SPLIT) ohi[base + o] = __float2half_rn(r);
    }
}

// ============================ launcher =======================================
extern "C" void kernel_launch(void* const* d_in, const int* in_sizes, int n_in,
                              void* d_out, int out_size)
{
    const float* x     = (const float*)d_in[0];
    const float* Wq    = (const float*)d_in[1];
    const float* bq    = (const float*)d_in[2];
    const float* Wk    = (const float*)d_in[3];
    const float* bk    = (const float*)d_in[4];
    const float* Wv    = (const float*)d_in[5];
    const float* bv    = (const float*)d_in[6];
    const float* W1    = (const float*)d_in[7];
    const float* b1    = (const float*)d_in[8];
    const float* W2    = (const float*)d_in[9];
    const float* b2    = (const float*)d_in[10];
    const float* g1    = (const float*)d_in[11];
    const float* beta1 = (const float*)d_in[12];
    const float* g2    = (const float*)d_in[13];
    const float* beta2 = (const float*)d_in[14];
    float* out = (float*)d_out;

    fp16 *xhi, *Wqkvh, *W1Th, *W2Th;
    fp16 *QKVh, *VTh, *Sh, *Phi, *x1hi, *hhi;
    float *bqkv, *attnP, *x1, *fP;
    cudaGetSymbolAddress((void**)&xhi, g_xhi);
    cudaGetSymbolAddress((void**)&Wqkvh, g_Wqkvh);
    cudaGetSymbolAddress((void**)&bqkv, g_bqkv);
    cudaGetSymbolAddress((void**)&W1Th, g_W1Th);
    cudaGetSymbolAddress((void**)&W2Th, g_W2Th);
    cudaGetSymbolAddress((void**)&QKVh, g_QKVh);
    cudaGetSymbolAddress((void**)&VTh, g_VTh);
    cudaGetSymbolAddress((void**)&Sh, g_Sh);
    cudaGetSymbolAddress((void**)&Phi, g_Phi);
    cudaGetSymbolAddress((void**)&attnP, g_attnP);
    cudaGetSymbolAddress((void**)&x1, g_x1);
    cudaGetSymbolAddress((void**)&x1hi, g_x1hi);
    cudaGetSymbolAddress((void**)&hhi, g_hhi);
    cudaGetSymbolAddress((void**)&fP, g_fP);

    cudaFuncSetAttribute((const void*)mma_gemm_big<1, true>,  cudaFuncAttributeMaxDynamicSharedMemorySize, SM_GEMM);
    cudaFuncSetAttribute((const void*)mma_gemm_big<2, false>, cudaFuncAttributeMaxDynamicSharedMemorySize, SM_GEMM);
    cudaFuncSetAttribute((const void*)mma_gemm_big<3, false>, cudaFuncAttributeMaxDynamicSharedMemorySize, SM_GEMM);
    cudaFuncSetAttribute((const void*)mma_gemm_big<4, false>, cudaFuncAttributeMaxDynamicSharedMemorySize, SM_GEMM);

    const dim3 blk(256);
    const dim3 tblk(32, 8);
    const float att_scale = 1.0f / sqrtf((float)EMBED);

    // 0: weights transpose + bias concat + x conversion (single launch)
    mega_wsplit<<<12481, tblk>>>(Wq, Wk, Wv, W1, W2, x, bq, bk, bv,
                                 W1Th, W2Th, xhi, bqkv);
    // 1: fused QKV = x @ [Wq|Wk|Wv] + bias; Q,K -> hi, V -> VT (fused transpose)
    mma_gemm_big<1, true><<<dim3(NQKV / BT_N, TOK / BT_M, 1), blk, SM_GEMM>>>(
        xhi, EMBED, 0, Wqkvh, EMBED, 0,
        nullptr, QKVh, NQKV, 0, bqkv, 0.f, EMBED, 1, 0, VTh);
    // 2: scores = Q @ K^T * scale -> fp16
    mma_gemm_big<4, false><<<dim3(SEQ / BT_N, SEQ / BT_M, BATCH), blk, SM_GEMM>>>(
        QKVh, NQKV, (long)SEQ * NQKV,
        QKVh + EMBED, NQKV, (long)SEQ * NQKV,
        nullptr, Sh, SEQ, (long)SEQ * SEQ, nullptr, att_scale, EMBED, 1, 0, nullptr);
    // 3: softmax -> P
    softmax_kernel<<<TOK, blk>>>(Sh, Phi);
    // 4: attn partials = P @ V, split-K=2
    mma_gemm_big<2, false><<<dim3(EMBED / BT_N, SEQ / BT_M, BATCH * 2), blk, SM_GEMM>>>(
        Phi, SEQ, (long)SEQ * SEQ, VTh, SEQ, (long)EMBED * SEQ,
        attnP, nullptr, EMBED, (long)SEQ * EMBED, nullptr, 1.0f, SEQ / 2,
        2, (long)TOK * EMBED, nullptr);
    // 5: x1 = x + LN(attn0 + attn1)  (+ hi split)
    ln_residual_kernel<2, false, true><<<TOK, blk>>>(
        x, attnP, attnP + (long)TOK * EMBED, nullptr, nullptr, g1, beta1, x1, x1hi);
    // 6: h = gelu(x1 @ W1 + b1) -> hi
    mma_gemm_big<3, false><<<dim3(FF / BT_N, TOK / BT_M, 1), blk, SM_GEMM>>>(
        x1hi, EMBED, 0, W1Th, EMBED, 0,
        nullptr, hhi, FF, 0, b1, 0.f, EMBED, 1, 0, nullptr);
    // 7: f partials = h @ W2, split-K=3
    mma_gemm_big<2, false><<<dim3(EMBED / BT_N, TOK / BT_M, 3), blk, SM_GEMM>>>(
        hhi, FF, 0, W2Th, FF, 0,
        fP, nullptr, EMBED, 0, nullptr, 1.0f, FF / 3, 3, (long)TOK * EMBED, nullptr);
    // 8: out = x1 + LN(f0+f1+f2 + b2)
    ln_residual_kernel<3, true, false><<<TOK, blk>>>(
        x1, fP, fP + (long)TOK * EMBED, fP + 2L * TOK * EMBED, b2, g2, beta2,
        out, nullptr);
}

// round 17
// speedup vs baseline: 1.8253x; 1.0083x over previous
#include <cuda_runtime.h>
#include <cuda_fp16.h>
#include <math.h>
#include <stdint.h>

#define EMBED 768
#define FF    3072
#define BATCH 8
#define SEQ   1024
#define TOK   (BATCH * SEQ)   // 8192
#define NQKV  (3 * EMBED)     // 2304

typedef __half fp16;

// ============================ scratch buffers ================================
__device__ __align__(16) fp16  g_xhi[TOK * EMBED];
__device__ __align__(16) fp16  g_Wqkvh[(long)NQKV * EMBED];
__device__ __align__(16) float g_bqkv[NQKV];
__device__ __align__(16) fp16  g_W1Th[(long)FF * EMBED];
__device__ __align__(16) fp16  g_W2Th[(long)EMBED * FF];
__device__ __align__(16) fp16  g_QKVh[(long)TOK * NQKV];
__device__ __align__(16) fp16  g_VTh[(long)BATCH * EMBED * SEQ];
__device__ __align__(16) fp16  g_Sh[(long)BATCH * SEQ * SEQ];
__device__ __align__(16) fp16  g_Phi[(long)BATCH * SEQ * SEQ];
__device__ __align__(16) float g_attnP[2L * TOK * EMBED];
__device__ __align__(16) float g_x1[TOK * EMBED];
__device__ __align__(16) fp16  g_x1hi[TOK * EMBED];
__device__ __align__(16) fp16  g_hhi[(long)TOK * FF];
__device__ __align__(16) float g_fP[3L * TOK * EMBED];

// ============================ PTX helpers ====================================
__device__ __forceinline__ uint32_t smem_u32(const void* p) {
    uint32_t a;
    asm("{ .reg .u64 t; cvta.to.shared.u64 t, %1; cvt.u32.u64 %0, t; }" : "=r"(a) : "l"(p));
    return a;
}
__device__ __forceinline__ void cp16(uint32_t dst, const void* src) {
    asm volatile("cp.async.cg.shared.global [%0], [%1], 16;" :: "r"(dst), "l"(src));
}
#define CP_COMMIT() asm volatile("cp.async.commit_group;" ::: "memory")

__device__ __forceinline__ void ldm_x4(uint32_t* r, uint32_t addr) {
    asm volatile("ldmatrix.sync.aligned.m8n8.x4.shared.b16 {%0,%1,%2,%3}, [%4];"
                 : "=r"(r[0]), "=r"(r[1]), "=r"(r[2]), "=r"(r[3]) : "r"(addr));
}
__device__ __forceinline__ void mma16816(float* d, const uint32_t* a, uint32_t b0, uint32_t b1) {
    asm volatile(
        "mma.sync.aligned.m16n8k16.row.col.f32.f16.f16.f32 "
        "{%0,%1,%2,%3}, {%4,%5,%6,%7}, {%8,%9}, {%0,%1,%2,%3};"
        : "+f"(d[0]), "+f"(d[1]), "+f"(d[2]), "+f"(d[3])
        : "r"(a[0]), "r"(a[1]), "r"(a[2]), "r"(a[3]), "r"(b0), "r"(b1));
}
#define SWZ128(o) ((o) ^ (((o) >> 3) & 0x70))

__device__ __forceinline__ float gelu_exact(float v) {
    return 0.5f * v * (1.0f + erff(v * 0.7071067811865475f));
}
__device__ __forceinline__ ushort h2u(fp16 h) { return __half_as_ushort(h); }

// ============================ mma GEMM (1-pass fp16, 2 CTA/SM) ===============
// C[M,N] = Ahi[M,K] @ Bhi[N,K]^T  (both K-major row-major)
// CTA 128x128, 256 threads (8 warps: 2M x 4N, warp tile 64x32), BK=64,
// 3 stages x 32KB = 96KB -> 2 CTAs/SM.
// Per chunk (proven order): wait_group -> barrier -> issue c+2 -> compute.
// blockIdx.z = batch*ksplit + split; K = per-split length.
// EPI: 1 bias->hi | 2 scale->fp32 | 3 bias+gelu->hi | 4 scale->fp16
// VOUT (with EPI=1): CTAs with col0>=1536 write transposed VT instead.
#define BT_M 128
#define BT_N 128
#define BK   64
#define STG  32768u            // A 16K | B 16K
#define BOFF 16384u
#define SM_GEMM (3 * 32768)

template <int EPI, bool VOUT>
__global__ __launch_bounds__(256, 2)
void mma_gemm_big(const fp16* __restrict__ Ahi, long ldA, long bsA,
                  const fp16* __restrict__ Bhi, long ldB, long bsB,
                  float* __restrict__ C, fp16* __restrict__ Chi,
                  long ldC, long bsC, const float* __restrict__ bias, float scale, int K,
                  int ksplit, long spStrideC, fp16* __restrict__ VTh)
{
    extern __shared__ char smem[];
    const uint32_t sbase = smem_u32(smem);
    const int tid  = threadIdx.x;
    const int bz   = blockIdx.z;
    const int sp   = bz % ksplit;
    const int bt   = bz / ksplit;
    const long koff = (long)sp * K;
    const int row0 = blockIdx.y * BT_M;
    const int col0 = blockIdx.x * BT_N;

    const fp16* Ah = Ahi + (long)bt * bsA + koff;
    const fp16* Bh = Bhi + (long)bt * bsB + koff;

    const int NC = K / BK;

    auto load_stage = [&](int buf, int k0) {
        const uint32_t sb = sbase + (uint32_t)buf * STG;
        #pragma unroll
        for (int i = 0; i < 4; i++) {            // A: 1024 granules
            const int g = tid + 256 * i;
            const int r = g >> 3, c = g & 7;
            const uint32_t off = SWZ128((uint32_t)(r * 128 + c * 16));
            cp16(sb + off, Ah + (long)(row0 + r) * ldA + k0 + c * 8);
        }
        #pragma unroll
        for (int i = 0; i < 4; i++) {            // B: 1024 granules
            const int g = tid + 256 * i;
            const int r = g >> 3, c = g & 7;
            const uint32_t off = SWZ128((uint32_t)(r * 128 + c * 16));
            cp16(sb + BOFF + off, Bh + (long)(col0 + r) * ldB + k0 + c * 8);
        }
    };

    load_stage(0, 0);      CP_COMMIT();
    if (NC > 1) { load_stage(1, BK); CP_COMMIT(); }

    const int w    = tid >> 5;
    const int lane = tid & 31;
    const int wm   = w & 1;            // rows wm*64
    const int wn   = w >> 1;           // cols wn*32
    const int q    = lane >> 3;
    const int r8   = lane & 7;

    const int bNN = wn * 32 + (q >> 1) * 8 + r8;   // + p*16
    const int bAR = wm * 64 + (q & 1) * 8 + r8;    // + am*16
    const int bAC = (q >> 1);                      // + 2*ks
    const int bBC = (q & 1);                       // + 2*ks

    float acc[4][4][4];
    #pragma unroll
    for (int i = 0; i < 4; i++)
        #pragma unroll
        for (int j = 0; j < 4; j++)
            #pragma unroll
            for (int v = 0; v < 4; v++) acc[i][j][v] = 0.0f;

    for (int c = 0; c < NC; c++) {
        if (c + 1 < NC) asm volatile("cp.async.wait_group 1;" ::: "memory");
        else            asm volatile("cp.async.wait_group 0;" ::: "memory");
        __syncthreads();                          // all threads' group c landed
        if (c + 2 < NC) {
            load_stage((c + 2) % 3, (c + 2) * BK);   // buffer freed by chunk c-1
            CP_COMMIT();
        }

        const uint32_t sb  = sbase + (uint32_t)(c % 3) * STG;
        const uint32_t sbB = sb + BOFF;

        #pragma unroll
        for (int ks = 0; ks < 4; ks++) {
            uint32_t bf[2][4];
            #pragma unroll
            for (int p = 0; p < 2; p++)
                ldm_x4(bf[p], sbB + SWZ128((uint32_t)((bNN + p * 16) * 128 + (2 * ks + bBC) * 16)));
            #pragma unroll
            for (int am = 0; am < 4; am++) {
                uint32_t af[4];
                ldm_x4(af, sb + SWZ128((uint32_t)((bAR + am * 16) * 128 + (2 * ks + bAC) * 16)));
                #pragma unroll
                for (int bn = 0; bn < 4; bn++) {
                    const int p = bn >> 1, hf = (bn & 1) * 2;
                    mma16816(acc[am][bn], af, bf[p][hf], bf[p][hf + 1]);
                }
            }
        }
    }

    // -------- epilogue --------
    const int gg = lane >> 2, t = lane & 3;
    float* Cp = (EPI == 2) ? C + (long)bt * bsC + (long)sp * spStrideC : nullptr;
    fp16* Hp  = (EPI == 1 || EPI == 3 || EPI == 4) ? Chi + (long)bt * bsC : nullptr;
    const bool vout = VOUT && (col0 >= 2 * EMBED);

    #pragma unroll
    for (int am = 0; am < 4; am++) {
        const long r0 = row0 + wm * 64 + am * 16 + gg;
        const long r1 = r0 + 8;
        #pragma unroll
        for (int bn = 0; bn < 4; bn++) {
            const int col = col0 + wn * 32 + bn * 8 + 2 * t;
            float v[4];
            #pragma unroll
            for (int i = 0; i < 4; i++) v[i] = acc[am][bn][i];
            if (EPI == 2 || EPI == 4) {
                #pragma unroll
                for (int i = 0; i < 4; i++) v[i] *= scale;
            } else {
                const float b0 = __ldg(&bias[col]);
                const float b1 = __ldg(&bias[col + 1]);
                v[0] += b0; v[1] += b1; v[2] += b0; v[3] += b1;
                if (EPI == 3) {
                    #pragma unroll
                    for (int i = 0; i < 4; i++) v[i] = gelu_exact(v[i]);
                }
            }
            if (EPI == 2) {
                *(float2*)(Cp + r0 * ldC + col) = make_float2(v[0], v[1]);
                *(float2*)(Cp + r1 * ldC + col) = make_float2(v[2], v[3]);
            } else if (vout) {
                const int e = col - 2 * EMBED;
                const long b0i = (r0 >> 10) * (long)EMBED * SEQ;
                const long s0 = r0 & 1023;
                const long b1i = (r1 >> 10) * (long)EMBED * SEQ;
                const long s1 = r1 & 1023;
                #pragma unroll
                for (int i = 0; i < 4; i++) {
                    const long o = ((i < 2) ? (b0i + s0) : (b1i + s1)) + (long)(e + (i & 1)) * SEQ;
                    VTh[o] = __float2half_rn(v[i]);
                }
            } else {
                fp16 a0 = __float2half_rn(v[0]), a1 = __float2half_rn(v[1]);
                fp16 a2 = __float2half_rn(v[2]), a3 = __float2half_rn(v[3]);
                *(ushort2*)(Hp + r0 * ldC + col) = make_ushort2(h2u(a0), h2u(a1));
                *(ushort2*)(Hp + r1 * ldC + col) = make_ushort2(h2u(a2), h2u(a3));
            }
        }
    }
}

// ============================ glue kernels ===================================
// One launch: transpose all 5 weights [R,C]->[C,R] fp16 (64x32 tiles, ushort2
// coalesced stores), bias concat, and x -> fp16 conversion.
// Block map: [0,864) Wq/Wk/Wv | [864,2016) W1 | [2016,3168) W2 |
//            3168 bias | [3169, 3169+6144) x conversion.
__global__ __launch_bounds__(256)
void mega_wsplit(const float* __restrict__ Wq, const float* __restrict__ Wk,
                 const float* __restrict__ Wv, const float* __restrict__ W1,
                 const float* __restrict__ W2, const float* __restrict__ x,
                 const float* __restrict__ bq, const float* __restrict__ bk,
                 const float* __restrict__ bv,
                 fp16* __restrict__ W1h, fp16* __restrict__ W2h,
                 fp16* __restrict__ xhi, float* __restrict__ bqkv)
{
    const int tflat = threadIdx.y * 32 + threadIdx.x;
    const int blk = blockIdx.x;
    if (blk >= 3169) {                           // x conversion: 6144 blocks
        const long i4 = (long)(blk - 3169) * 256 + tflat;   // float4 index
        float4 v = ((const float4*)x)[i4];
        unsigned short h[4];
        h[0] = __half_as_ushort(__float2half_rn(v.x));
        h[1] = __half_as_ushort(__float2half_rn(v.y));
        h[2] = __half_as_ushort(__float2half_rn(v.z));
        h[3] = __half_as_ushort(__float2half_rn(v.w));
        ((uint2*)xhi)[i4] = *(uint2*)h;
        return;
    }
    if (blk == 3168) {
        for (int i = tflat; i < NQKV; i += 256)
            bqkv[i] = (i < EMBED) ? bq[i] : (i < 2 * EMBED) ? bk[i - EMBED] : bv[i - 2 * EMBED];
        return;
    }
    // transpose: 64 input rows x 32 input cols per block
    const float* in; fp16* hi;
    int R, C, bx, by;
    if (blk < 864) {                             // Wq/Wk/Wv: 288 blocks each
        const int ww = blk / 288, loc = blk % 288;
        in = (ww == 0) ? Wq : (ww == 1) ? Wk : Wv;
        hi = g_Wqkvh + (long)ww * EMBED * EMBED;
        R = EMBED; C = EMBED; bx = loc % 24; by = loc / 24;       // 24 x 12
    } else if (blk < 2016) {                     // W1 [768,3072]: 96 x 12
        const int loc = blk - 864;
        in = W1; hi = W1h;
        R = EMBED; C = FF; bx = loc % 96; by = loc / 96;
    } else {                                     // W2 [3072,768]: 24 x 48
        const int loc = blk - 2016;
        in = W2; hi = W2h;
        R = FF; C = EMBED; bx = loc % 24; by = loc / 24;
    }
    __shared__ float tshr[64][33];
    const int tx = threadIdx.x, ty = threadIdx.y;
    const int c0 = bx * 32;
    const int r0 = by * 64;
    #pragma unroll
    for (int i = 0; i < 8; i++)
        tshr[ty + i * 8][tx] = in[(long)(r0 + ty + i * 8) * C + c0 + tx];
    __syncthreads();
    #pragma unroll
    for (int j = 0; j < 4; j++) {
        const int cl = ty + j * 8;
        const float v0 = tshr[2 * tx][cl];
        const float v1 = tshr[2 * tx + 1][cl];
        const long o = (long)(c0 + cl) * R + r0 + 2 * tx;
        *(ushort2*)(hi + o) = make_ushort2(
            __half_as_ushort(__float2half_rn(v0)),
            __half_as_ushort(__float2half_rn(v1)));
    }
}

// rowwise softmax over 1024 fp16 -> fp16, half2 vectorized
__global__ __launch_bounds__(256)
void softmax_kernel(const __half2* __restrict__ S, __half2* __restrict__ Phi)
{
    const __half2* row = S + (long)blockIdx.x * (SEQ / 2);
    const int tid = threadIdx.x;
    float2 v[2];
    float m = -1e30f;
    #pragma unroll
    for (int j = 0; j < 2; j++) {
        v[j] = __half22float2(row[tid + 256 * j]);
        m = fmaxf(m, fmaxf(v[j].x, v[j].y));
    }
    __shared__ float red[8];
    #pragma unroll
    for (int o = 16; o > 0; o >>= 1) m = fmaxf(m, __shfl_xor_sync(0xffffffffu, m, o));
    if ((tid & 31) == 0) red[tid >> 5] = m;
    __syncthreads();
    m = red[0];
    #pragma unroll
    for (int i = 1; i < 8; i++) m = fmaxf(m, red[i]);
    float s = 0.0f;
    #pragma unroll
    for (int j = 0; j < 2; j++) {
        v[j].x = __expf(v[j].x - m);
        v[j].y = __expf(v[j].y - m);
        s += v[j].x + v[j].y;
    }
    __syncthreads();
    #pragma unroll
    for (int o = 16; o > 0; o >>= 1) s += __shfl_xor_sync(0xffffffffu, s, o);
    if ((tid & 31) == 0) red[tid >> 5] = s;
    __syncthreads();
    s = 0.0f;
    #pragma unroll
    for (int i = 0; i < 8; i++) s += red[i];
    const float inv = 1.0f / s;
    __half2* ph = Phi + (long)blockIdx.x * (SEQ / 2);
    #pragma unroll
    for (int j = 0; j < 2; j++)
        ph[tid + 256 * j] = __floats2half2_rn(v[j].x * inv, v[j].y * inv);
}

// out = xin + LN(t0 (+t1) (+t2) (+bias)) * g + beta;  optional hi split out.
template <int NT, bool HASB, bool SPLIT>
__global__ __launch_bounds__(256)
void ln_residual_kernel(const float* __restrict__ xin,
                        const float* __restrict__ t0, const float* __restrict__ t1,
                        const float* __restrict__ t2, const float* __restrict__ bvec,
                        const float* __restrict__ g, const float* __restrict__ beta,
                        float* __restrict__ out, fp16* __restrict__ ohi)
{
    const long base = (long)blockIdx.x * EMBED;
    const int tid = threadIdx.x;
    float vv[3];
    #pragma unroll
    for (int j = 0; j < 3; j++) {
        const int o = tid + j * 256;
        float v = t0[base + o];
        if (NT >= 2) v += t1[base + o];
        if (NT >= 3) v += t2[base + o];
        if (HASB)    v += bvec[o];
        vv[j] = v;
    }
    float s = vv[0] + vv[1] + vv[2];
    float q = vv[0] * vv[0] + vv[1] * vv[1] + vv[2] * vv[2];
    __shared__ float rs[8], rq[8];
    #pragma unroll
    for (int o = 16; o > 0; o >>= 1) {
        s += __shfl_xor_sync(0xffffffffu, s, o);
        q += __shfl_xor_sync(0xffffffffu, q, o);
    }
    if ((tid & 31) == 0) { rs[tid >> 5] = s; rq[tid >> 5] = q; }
    __syncthreads();
    s = 0.0f; q = 0.0f;
    #pragma unroll
    for (int i = 0; i < 8; i++) { s += rs[i]; q += rq[i]; }
    const float mu  = s * (1.0f / EMBED);
    const float var = q * (1.0f / EMBED) - mu * mu;
    const float inv = rsqrtf(var + 1e-5f);
    #pragma unroll
    for (int j = 0; j < 3; j++) {
        const int o = tid + j * 256;
        float r = xin[base + o] + (vv[j] - mu) * inv * g[o] + beta[o];
        out[base + o] = r;
        if (SPLIT) ohi[base + o] = __float2half_rn(r);
    }
}

// ============================ launcher =======================================
extern "C" void kernel_launch(void* const* d_in, const int* in_sizes, int n_in,
                              void* d_out, int out_size)
{
    const float* x     = (const float*)d_in[0];
    const float* Wq    = (const float*)d_in[1];
    const float* bq    = (const float*)d_in[2];
    const float* Wk    = (const float*)d_in[3];
    const float* bk    = (const float*)d_in[4];
    const float* Wv    = (const float*)d_in[5];
    const float* bv    = (const float*)d_in[6];
    const float* W1    = (const float*)d_in[7];
    const float* b1    = (const float*)d_in[8];
    const float* W2    = (const float*)d_in[9];
    const float* b2    = (const float*)d_in[10];
    const float* g1    = (const float*)d_in[11];
    const float* beta1 = (const float*)d_in[12];
    const float* g2    = (const float*)d_in[13];
    const float* beta2 = (const float*)d_in[14];
    float* out = (float*)d_out;

    fp16 *xhi, *Wqkvh, *W1Th, *W2Th;
    fp16 *QKVh, *VTh, *Sh, *Phi, *x1hi, *hhi;
    float *bqkv, *attnP, *x1, *fP;
    cudaGetSymbolAddress((void**)&xhi, g_xhi);
    cudaGetSymbolAddress((void**)&Wqkvh, g_Wqkvh);
    cudaGetSymbolAddress((void**)&bqkv, g_bqkv);
    cudaGetSymbolAddress((void**)&W1Th, g_W1Th);
    cudaGetSymbolAddress((void**)&W2Th, g_W2Th);
    cudaGetSymbolAddress((void**)&QKVh, g_QKVh);
    cudaGetSymbolAddress((void**)&VTh, g_VTh);
    cudaGetSymbolAddress((void**)&Sh, g_Sh);
    cudaGetSymbolAddress((void**)&Phi, g_Phi);
    cudaGetSymbolAddress((void**)&attnP, g_attnP);
    cudaGetSymbolAddress((void**)&x1, g_x1);
    cudaGetSymbolAddress((void**)&x1hi, g_x1hi);
    cudaGetSymbolAddress((void**)&hhi, g_hhi);
    cudaGetSymbolAddress((void**)&fP, g_fP);

    cudaFuncSetAttribute((const void*)mma_gemm_big<1, true>,  cudaFuncAttributeMaxDynamicSharedMemorySize, SM_GEMM);
    cudaFuncSetAttribute((const void*)mma_gemm_big<2, false>, cudaFuncAttributeMaxDynamicSharedMemorySize, SM_GEMM);
    cudaFuncSetAttribute((const void*)mma_gemm_big<3, false>, cudaFuncAttributeMaxDynamicSharedMemorySize, SM_GEMM);
    cudaFuncSetAttribute((const void*)mma_gemm_big<4, false>, cudaFuncAttributeMaxDynamicSharedMemorySize, SM_GEMM);

    const dim3 blk(256);
    const dim3 tblk(32, 8);
    const float att_scale = 1.0f / sqrtf((float)EMBED);

    // 0: weights transpose + bias concat + x conversion (single launch)
    mega_wsplit<<<9313, tblk>>>(Wq, Wk, Wv, W1, W2, x, bq, bk, bv,
                                W1Th, W2Th, xhi, bqkv);
    // 1: fused QKV = x @ [Wq|Wk|Wv] + bias; Q,K -> hi, V -> VT (fused transpose)
    mma_gemm_big<1, true><<<dim3(NQKV / BT_N, TOK / BT_M, 1), blk, SM_GEMM>>>(
        xhi, EMBED, 0, Wqkvh, EMBED, 0,
        nullptr, QKVh, NQKV, 0, bqkv, 0.f, EMBED, 1, 0, VTh);
    // 2: scores = Q @ K^T * scale -> fp16
    mma_gemm_big<4, false><<<dim3(SEQ / BT_N, SEQ / BT_M, BATCH), blk, SM_GEMM>>>(
        QKVh, NQKV, (long)SEQ * NQKV,
        QKVh + EMBED, NQKV, (long)SEQ * NQKV,
        nullptr, Sh, SEQ, (long)SEQ * SEQ, nullptr, att_scale, EMBED, 1, 0, nullptr);
    // 3: softmax -> P (half2)
    softmax_kernel<<<TOK, blk>>>((const __half2*)Sh, (__half2*)Phi);
    // 4: attn partials = P @ V, split-K=2
    mma_gemm_big<2, false><<<dim3(EMBED / BT_N, SEQ / BT_M, BATCH * 2), blk, SM_GEMM>>>(
        Phi, SEQ, (long)SEQ * SEQ, VTh, SEQ, (long)EMBED * SEQ,
        attnP, nullptr, EMBED, (long)SEQ * EMBED, nullptr, 1.0f, SEQ / 2,
        2, (long)TOK * EMBED, nullptr);
    // 5: x1 = x + LN(attn0 + attn1)  (+ hi split)
    ln_residual_kernel<2, false, true><<<TOK, blk>>>(
        x, attnP, attnP + (long)TOK * EMBED, nullptr, nullptr, g1, beta1, x1, x1hi);
    // 6: h = gelu(x1 @ W1 + b1) -> hi
    mma_gemm_big<3, false><<<dim3(FF / BT_N, TOK / BT_M, 1), blk, SM_GEMM>>>(
        x1hi, EMBED, 0, W1Th, EMBED, 0,
        nullptr, hhi, FF, 0, b1, 0.f, EMBED, 1, 0, nullptr);
    // 7: f partials = h @ W2, split-K=3
    mma_gemm_big<2, false><<<dim3(EMBED / BT_N, TOK / BT_M, 3), blk, SM_GEMM>>>(
        hhi, FF, 0, W2Th, FF, 0,
        fP, nullptr, EMBED, 0, nullptr, 1.0f, FF / 3, 3, (long)TOK * EMBED, nullptr);
    // 8: out = x1 + LN(f0+f1+f2 + b2)
    ln_residual_kernel<3, true, false><<<TOK, blk>>>(
        x1, fP, fP + (long)TOK * EMBED, fP + 2L * TOK * EMBED, b2, g2, beta2,
        out, nullptr);
}